// round 6
// baseline (speedup 1.0000x reference)
#include <cuda_runtime.h>
#include <cuda_bf16.h>
#include <cstdint>

// ---------------- problem constants ----------------
#define LLEN   256
#define DDIM   1024
#define TOKENS 1024            // B*L
#define BLD    (1024*1024)     // TOKENS*D
#define XDB    (1024*96)       // TOKENS*96
#define LQN    77
#define MH     308             // B*LQ
#define OUTF   768

#define BKK 16
#define BNN 64

// ---------------- scratch buffers (no runtime allocation allowed) ----------------
__device__ float g_res [BLD];
__device__ float g_h   [BLD];
__device__ float g_hn  [BLD];
__device__ float g_xz  [4*BLD];     // [tok][4096]: dir0 x|z, dir1 x|z
__device__ float g_xc  [2*BLD];     // conv+silu output per dir
__device__ float g_dt  [2*BLD];
__device__ float g_xdbl[2*XDB];     // [dir][tok][96]
__device__ float g_yp  [2*BLD];     // [tok][2048]: dir0 | dir1 (for fused out-GEMM)
__device__ float g_kv  [2*BLD];     // [tok][2048]
__device__ float g_o   [MH*1024];
__device__ float g_po  [MH*1024];
__device__ float g_s1  [MH*1536];

// ---------------- helpers ----------------
__device__ __forceinline__ unsigned long long f2pack(float x, float y){
    unsigned long long r;
    asm("mov.b64 %0, {%1, %2};" : "=l"(r) : "f"(x), "f"(y));
    return r;
}
__device__ __forceinline__ void f2unpack(float& x, float& y, unsigned long long p){
    asm("mov.b64 {%0, %1}, %2;" : "=f"(x), "=f"(y) : "l"(p));
}
__device__ __forceinline__ void f2fma(unsigned long long& d, unsigned long long a, unsigned long long b){
    asm("fma.rn.f32x2 %0, %1, %2, %0;" : "+l"(d) : "l"(a), "l"(b));
}
__device__ __forceinline__ float siluf(float v){ return v / (1.f + __expf(-v)); }
__device__ __forceinline__ float softplusf(float v){ return v > 20.f ? v : log1pf(__expf(v)); }

__device__ __forceinline__ float block_sum(float v, float* red){
    #pragma unroll
    for (int o = 16; o; o >>= 1) v += __shfl_xor_sync(0xffffffffu, v, o);
    int w = threadIdx.x >> 5, ln = threadIdx.x & 31;
    if (ln == 0) red[w] = v;
    __syncthreads();
    float t = (threadIdx.x < 8) ? red[threadIdx.x] : 0.f;
    #pragma unroll
    for (int o = 4; o; o >>= 1) t += __shfl_xor_sync(0xffffffffu, t, o);
    if (threadIdx.x == 0) red[0] = t;
    __syncthreads();
    t = red[0];
    __syncthreads();
    return t;
}
__device__ __forceinline__ float block_max(float v, float* red){
    #pragma unroll
    for (int o = 16; o; o >>= 1) v = fmaxf(v, __shfl_xor_sync(0xffffffffu, v, o));
    int w = threadIdx.x >> 5, ln = threadIdx.x & 31;
    if (ln == 0) red[w] = v;
    __syncthreads();
    float t = (threadIdx.x < 8) ? red[threadIdx.x] : -3.0e38f;
    #pragma unroll
    for (int o = 4; o; o >>= 1) t = fmaxf(t, __shfl_xor_sync(0xffffffffu, t, o));
    if (threadIdx.x == 0) red[0] = t;
    __syncthreads();
    t = red[0];
    __syncthreads();
    return t;
}

// ---------------- GEMM: C[M,N] = A[M,K] @ W[N,K]^T  (row-major everywhere) ----------------
// Packed-f32x2 (FFMA2) accumulation for full-rate fp32 on sm_103a.
// BMT in {128, 32}; BN=64, BK=16, 256 threads; thread tile (BMT/16) x 4.
// Optional: W split at K1 (second weight matrix W2), bias over N, activation,
// split-write epilogue for the final (a,b) output, blockIdx.z strides for batching dirs.
template<int BMT, int DOBIAS, int ACT, int SPLIT>
__global__ void __launch_bounds__(256) gemm_k(
    const float* __restrict__ A, int lda, long long sA,
    const float* __restrict__ W, int ldw, long long sW,
    const float* __restrict__ W2, int K1,
    const float* __restrict__ bias, long long sB,
    float* __restrict__ C, int ldc, long long sC,
    int M, int N, int K)
{
    constexpr int MP = BMT / 32;           // accumulator m-pairs per thread
    __shared__ __align__(16) float As[BKK][BMT + 4];
    __shared__ __align__(16) float Ws[BKK][BNN + 2];

    if (sA) A += (size_t)blockIdx.z * sA;
    if (sW) W += (size_t)blockIdx.z * sW;
    if (sC) C += (size_t)blockIdx.z * sC;
    if (DOBIAS && sB) bias += (size_t)blockIdx.z * sB;

    const int tid  = threadIdx.x;
    const int tx   = tid & 15;
    const int ty   = tid >> 4;
    const int bm   = blockIdx.y * BMT;
    const int bn   = blockIdx.x * BNN;
    const int kcol = (tid & 3) * 4;
    const int tyB  = ty * (BMT / 16);
    const int tx4  = tx * 4;

    unsigned long long acc[MP][4];
    #pragma unroll
    for (int p = 0; p < MP; ++p)
        #pragma unroll
        for (int j = 0; j < 4; ++j) acc[p][j] = 0ull;

    for (int k0 = 0; k0 < K; k0 += BKK) {
        const float* Wp = W;
        int kw = k0;
        if (K1 && k0 >= K1) { Wp = W2; kw = k0 - K1; }

        // --- load A tile (transposed into As[k][m]) ---
        #pragma unroll
        for (int h = 0; h < (BMT * 4 + 255) / 256; ++h) {
            int f = tid + h * 256;
            if (f < BMT * 4) {
                int r  = f >> 2;
                int kc = (f & 3) * 4;
                int m  = bm + r;
                float4 av = make_float4(0.f, 0.f, 0.f, 0.f);
                if (m < M) av = *(const float4*)(A + (size_t)m * lda + k0 + kc);
                As[kc + 0][r] = av.x; As[kc + 1][r] = av.y;
                As[kc + 2][r] = av.z; As[kc + 3][r] = av.w;
            }
        }
        // --- load W tile (transposed + bank swizzle into Ws[k][n']) ---
        {
            int wn = tid >> 2;
            int n  = bn + wn;
            float4 wv = make_float4(0.f, 0.f, 0.f, 0.f);
            if (n < N) wv = *(const float4*)(Wp + (size_t)n * ldw + kw + kcol);
            int np = wn + ((wn >> 5) << 1);   // avoid 2-way conflicts at n>=32
            Ws[kcol + 0][np] = wv.x; Ws[kcol + 1][np] = wv.y;
            Ws[kcol + 2][np] = wv.z; Ws[kcol + 3][np] = wv.w;
        }
        __syncthreads();

        #pragma unroll
        for (int kk = 0; kk < BKK; ++kk) {
            unsigned long long av[MP];
            #pragma unroll
            for (int p = 0; p < MP; ++p)
                av[p] = *(const unsigned long long*)&As[kk][tyB + 2 * p];
            #pragma unroll
            for (int j = 0; j < 4; ++j) {
                int nb = tx4 + j;
                float bv = Ws[kk][nb + ((nb >> 5) << 1)];
                unsigned long long bb = f2pack(bv, bv);
                #pragma unroll
                for (int p = 0; p < MP; ++p) f2fma(acc[p][j], av[p], bb);
            }
        }
        __syncthreads();
    }

    // --- epilogue ---
    #pragma unroll
    for (int p = 0; p < MP; ++p) {
        #pragma unroll
        for (int j = 0; j < 4; ++j) {
            float x0, x1;
            f2unpack(x0, x1, acc[p][j]);
            int col = bn + tx4 + j;
            int m0  = bm + tyB + 2 * p;
            if (col < N) {
                float bz = DOBIAS ? bias[col] : 0.f;
                float r0 = x0 + bz, r1 = x1 + bz;
                if (ACT == 1)      { r0 = siluf(r0);     r1 = siluf(r1); }
                else if (ACT == 2) { r0 = softplusf(r0); r1 = softplusf(r1); }
                if (SPLIT) {
                    // final output: s[:, :768] -> out[0..], s[:, 768:] -> out[MH*768..]
                    if (m0 < M) {
                        if (col < OUTF) C[(size_t)m0 * OUTF + col] = r0;
                        else            C[(size_t)MH * OUTF + (size_t)m0 * OUTF + (col - OUTF)] = r0;
                    }
                    if (m0 + 1 < M) {
                        if (col < OUTF) C[(size_t)(m0 + 1) * OUTF + col] = r1;
                        else            C[(size_t)MH * OUTF + (size_t)(m0 + 1) * OUTF + (col - OUTF)] = r1;
                    }
                } else {
                    if (m0 < M)     C[(size_t)m0 * ldc + col]       = r0;
                    if (m0 + 1 < M) C[(size_t)(m0 + 1) * ldc + col] = r1;
                }
            }
        }
    }
}

// ---------------- residual-add + LayerNorm(*w) ----------------
__global__ void __launch_bounds__(256) ln_k(const float* __restrict__ add,
                                            float* __restrict__ res,
                                            const float* __restrict__ w,
                                            float* __restrict__ out)
{
    __shared__ float red[8];
    int t = blockIdx.x;
    size_t base = (size_t)t * DDIM;
    int tid = threadIdx.x;
    float v[4];
    #pragma unroll
    for (int j = 0; j < 4; ++j) {
        int d = j * 256 + tid;
        float r = res[base + d];
        if (add) { r += add[base + d]; res[base + d] = r; }
        v[j] = r;
    }
    float s = v[0] + v[1] + v[2] + v[3];
    s = block_sum(s, red);
    float mean = s * (1.f / DDIM);
    float q = 0.f;
    #pragma unroll
    for (int j = 0; j < 4; ++j) { float d0 = v[j] - mean; q += d0 * d0; }
    q = block_sum(q, red);
    float inv = rsqrtf(q * (1.f / DDIM) + 1e-5f);
    #pragma unroll
    for (int j = 0; j < 4; ++j) {
        int d = j * 256 + tid;
        out[base + d] = (v[j] - mean) * inv * w[d];
    }
}

// ---------------- depthwise conv (dir0 causal, dir1 anti-causal) + bias + silu ----------------
__global__ void __launch_bounds__(256) conv_k(const float* __restrict__ cw,
                                              const float* __restrict__ cb,
                                              int layer)
{
    int g = blockIdx.x * 256 + threadIdx.x;
    int tok = g >> 10, d = g & 1023;
    int b = tok >> 8, t = tok & 255;
    const float* xz_b = g_xz + (size_t)b * 256 * 4096;
    // forward (causal: window t-3..t)
    {
        const float* w = cw + ((size_t)(layer * 2 + 0) * 1024 + d) * 4;
        float a = cb[(size_t)(layer * 2 + 0) * 1024 + d];
        #pragma unroll
        for (int j = 0; j < 4; ++j) {
            int ts = t - 3 + j;
            if (ts >= 0) a = fmaf(w[j], xz_b[(size_t)ts * 4096 + d], a);
        }
        g_xc[(size_t)tok * 1024 + d] = siluf(a);
    }
    // backward (anti-causal in original coords: window t..t+3, reversed taps)
    {
        const float* w = cw + ((size_t)(layer * 2 + 1) * 1024 + d) * 4;
        float a = cb[(size_t)(layer * 2 + 1) * 1024 + d];
        #pragma unroll
        for (int j = 0; j < 4; ++j) {
            int ts = t + 3 - j;
            if (ts <= 255) a = fmaf(w[j], xz_b[(size_t)ts * 4096 + 2048 + d], a);
        }
        g_xc[(size_t)BLD + (size_t)tok * 1024 + d] = siluf(a);
    }
}

// ---------------- selective scan (dir0 ascending t, dir1 descending t) ----------------
// Fuses +x*D_p and *silu(z); writes interleaved [tok][2048] for the fused out-GEMM.
__global__ void __launch_bounds__(64) scan_k(const float* __restrict__ A_log,
                                             const float* __restrict__ D_p,
                                             int layer)
{
    int dir = blockIdx.z, b = blockIdx.y;
    int d = blockIdx.x * 64 + threadIdx.x;
    size_t pbase = (size_t)((layer * 2 + dir) * 1024 + d);
    float Ar[16];
    const float* al = A_log + pbase * 16;
    #pragma unroll
    for (int n = 0; n < 16; ++n) Ar[n] = -__expf(al[n]);
    float Dp = D_p[pbase];
    float h[16];
    #pragma unroll
    for (int n = 0; n < 16; ++n) h[n] = 0.f;

    const float* dt_p = g_dt + (size_t)dir * BLD + (size_t)b * 256 * 1024 + d;
    const float* x_p  = g_xc + (size_t)dir * BLD + (size_t)b * 256 * 1024 + d;
    const float* z_p  = g_xz + (size_t)b * 256 * 4096 + dir * 2048 + 1024 + d;
    const float* bc   = g_xdbl + (size_t)dir * XDB + (size_t)b * 256 * 96;
    float* y_p = g_yp + (size_t)b * 256 * 2048 + dir * 1024 + d;

    for (int s = 0; s < 256; ++s) {
        int t = dir ? (255 - s) : s;
        float dt = dt_p[(size_t)t * 1024];
        float xv = x_p [(size_t)t * 1024];
        float zv = z_p [(size_t)t * 4096];
        const float* xd = bc + t * 96;
        float dx = dt * xv;
        float y = 0.f;
        #pragma unroll
        for (int n = 0; n < 16; ++n) {
            float wv = __expf(dt * Ar[n]);
            h[n] = fmaf(wv, h[n], dx * xd[64 + n]);
            y = fmaf(h[n], xd[80 + n], y);
        }
        y = fmaf(xv, Dp, y);
        y_p[(size_t)t * 2048] = y * siluf(zv);
    }
}

// ---------------- cross-attention: one block per (qi, head, batch) ----------------
__global__ void __launch_bounds__(256) attn_k(const float* __restrict__ q)
{
    __shared__ float qs[64];
    __shared__ float sc[256];
    __shared__ float po[4][64];
    __shared__ float red[8];
    int qi = blockIdx.x, hh = blockIdx.y, b = blockIdx.z;
    int tid = threadIdx.x;
    if (tid < 64) qs[tid] = q[((size_t)hh * LQN + qi) * 64 + tid];
    __syncthreads();
    float s;
    {   // scores: thread tid owns key position l=tid
        const float* kp = g_kv + ((size_t)(b * 256 + tid)) * 2048 + hh * 128;
        float a = 0.f;
        #pragma unroll 8
        for (int d0 = 0; d0 < 64; ++d0) a = fmaf(qs[d0], kp[d0], a);
        s = a * 0.125f;   // 1/sqrt(64)
    }
    float mx = block_max(s, red);
    float e  = __expf(s - mx);
    float Z  = block_sum(e, red);
    sc[tid] = e / Z;
    __syncthreads();
    // o = att @ v : 4 partial sums over l-quarters, coalesced over d
    int d0 = tid & 63, tq = tid >> 6;
    float a = 0.f;
    const float* vb = g_kv + ((size_t)(b * 256 + tq * 64)) * 2048 + hh * 128 + 64 + d0;
    for (int tt = 0; tt < 64; ++tt) a = fmaf(sc[tq * 64 + tt], vb[(size_t)tt * 2048], a);
    po[tq][d0] = a;
    __syncthreads();
    if (tid < 64) {
        float o = po[0][tid] + po[1][tid] + po[2][tid] + po[3][tid];
        g_o[((size_t)b * LQN + qi) * 1024 + hh * 64 + tid] = o;
    }
}

// ---------------- host-side launch helpers ----------------
template<int BMT, int DOBIAS, int ACT, int SPLIT>
static void gemm(const float* A, int lda, long long sA,
                 const float* W, int ldw, long long sW,
                 const float* W2, int K1,
                 const float* bias, long long sB,
                 float* C, int ldc, long long sC,
                 int M, int N, int K, int nz)
{
    dim3 grid((N + BNN - 1) / BNN, (M + BMT - 1) / BMT, nz);
    gemm_k<BMT, DOBIAS, ACT, SPLIT><<<grid, 256>>>(A, lda, sA, W, ldw, sW, W2, K1,
                                                   bias, sB, C, ldc, sC, M, N, K);
}

extern "C" void kernel_launch(void* const* d_in, const int* in_sizes, int n_in,
                              void* d_out, int out_size)
{
    (void)in_sizes; (void)n_in; (void)out_size;
    const float* x       = (const float*)d_in[0];
    const float* stem_W  = (const float*)d_in[1];
    const float* stem_b  = (const float*)d_in[2];
    const float* norm_w  = (const float*)d_in[3];
    const float* in_W    = (const float*)d_in[4];
    const float* conv_w  = (const float*)d_in[5];
    const float* conv_b  = (const float*)d_in[6];
    const float* xproj_W = (const float*)d_in[7];
    const float* dt_W    = (const float*)d_in[8];
    const float* dt_b    = (const float*)d_in[9];
    const float* A_log   = (const float*)d_in[10];
    const float* D_p     = (const float*)d_in[11];
    const float* out_W   = (const float*)d_in[12];
    const float* q       = (const float*)d_in[13];
    const float* kv_W    = (const float*)d_in[14];
    const float* po_W    = (const float*)d_in[15];
    const float* po_b    = (const float*)d_in[16];
    const float* h1_W    = (const float*)d_in[17];
    const float* h1_b    = (const float*)d_in[18];
    const float* h2_W    = (const float*)d_in[19];
    const float* h2_b    = (const float*)d_in[20];
    float* out = (float*)d_out;

    float *p_res, *p_h, *p_hn, *p_xz, *p_xc, *p_dt, *p_xdbl, *p_yp, *p_kv, *p_o, *p_po, *p_s1;
    cudaGetSymbolAddress((void**)&p_res,  g_res);
    cudaGetSymbolAddress((void**)&p_h,    g_h);
    cudaGetSymbolAddress((void**)&p_hn,   g_hn);
    cudaGetSymbolAddress((void**)&p_xz,   g_xz);
    cudaGetSymbolAddress((void**)&p_xc,   g_xc);
    cudaGetSymbolAddress((void**)&p_dt,   g_dt);
    cudaGetSymbolAddress((void**)&p_xdbl, g_xdbl);
    cudaGetSymbolAddress((void**)&p_yp,   g_yp);
    cudaGetSymbolAddress((void**)&p_kv,   g_kv);
    cudaGetSymbolAddress((void**)&p_o,    g_o);
    cudaGetSymbolAddress((void**)&p_po,   g_po);
    cudaGetSymbolAddress((void**)&p_s1,   g_s1);

    // stem: res = x @ stem_W^T + stem_b      (M=1024, N=1024, K=64)
    gemm<128,1,0,0>(x, 64, 0, stem_W, 64, 0, nullptr, 0, stem_b, 0,
                    p_res, 1024, 0, TOKENS, 1024, 64, 1);

    for (int i = 0; i < 16; ++i) {
        // res += h (i>0); hn = LN(res)*norm_w[i]
        ln_k<<<TOKENS, 256>>>(i == 0 ? nullptr : p_h, p_res,
                              norm_w + (size_t)i * 1024, p_hn);
        // xz (both dirs fused): N=4096
        gemm<128,0,0,0>(p_hn, 1024, 0, in_W + (size_t)i * 4096 * 1024, 1024, 0,
                        nullptr, 0, nullptr, 0, p_xz, 4096, 0, TOKENS, 4096, 1024, 1);
        // depthwise conv + silu (both dirs)
        conv_k<<<4096, 256>>>(conv_w, conv_b, i);
        // xproj: N=96, dirs via blockIdx.z
        gemm<32,0,0,0>(p_xc, 1024, BLD,
                       xproj_W + (size_t)i * 2 * 96 * 1024, 1024, (long long)96 * 1024,
                       nullptr, 0, nullptr, 0,
                       p_xdbl, 96, XDB, TOKENS, 96, 1024, 2);
        // dt = softplus(xdbl[:, :64] @ dt_W^T + dt_b): K=64, dirs via z
        gemm<128,1,2,0>(p_xdbl, 96, XDB,
                        dt_W + (size_t)i * 2 * 1024 * 64, 64, (long long)1024 * 64,
                        nullptr, 0,
                        dt_b + (size_t)i * 2 * 1024, 1024,
                        p_dt, 1024, BLD, TOKENS, 1024, 64, 2);
        // selective scan (+x*Dp, *silu(z)) -> interleaved yp
        scan_k<<<dim3(16, 4, 2), 64>>>(A_log, D_p, i);
        // h = yz0 @ outW0^T + yz1 @ outW1^T  (single K=2048 GEMM, split weights)
        gemm<128,0,0,0>(p_yp, 2048, 0,
                        out_W + (size_t)i * 2 * 1024 * 1024, 1024, 0,
                        out_W + (size_t)(i * 2 + 1) * 1024 * 1024, 1024,
                        nullptr, 0, p_h, 1024, 0, TOKENS, 1024, 2048, 1);
    }

    // final residual + LN
    ln_k<<<TOKENS, 256>>>(p_h, p_res, norm_w + (size_t)16 * 1024, p_hn);
    // kv projection: N=2048
    gemm<128,0,0,0>(p_hn, 1024, 0, kv_W, 1024, 0, nullptr, 0, nullptr, 0,
                    p_kv, 2048, 0, TOKENS, 2048, 1024, 1);
    // attention
    attn_k<<<dim3(LQN, 16, 4), 256>>>(q);
    // s = silu(o @ po_W^T + po_b)
    gemm<32,1,1,0>(p_o, 1024, 0, po_W, 1024, 0, nullptr, 0, po_b, 0,
                   p_po, 1024, 0, MH, 1024, 1024, 1);
    // s1 = silu(s @ h1_W^T + h1_b)
    gemm<32,1,1,0>(p_po, 1024, 0, h1_W, 1024, 0, nullptr, 0, h1_b, 0,
                   p_s1, 1536, 0, MH, 1536, 1024, 1);
    // s2 = s1 @ h2_W^T + h2_b, split-written as (a | b) into d_out
    gemm<32,1,0,1>(p_s1, 1536, 0, h2_W, 1536, 0, nullptr, 0, h2_b, 0,
                   out, 0, 0, MH, 1536, 1536, 1);
}

// round 7
// speedup vs baseline: 1.3308x; 1.3308x over previous
#include <cuda_runtime.h>
#include <cuda_bf16.h>
#include <cstdint>

// ---------------- problem constants ----------------
#define LLEN   256
#define DDIM   1024
#define TOKENS 1024            // B*L
#define BLD    (1024*1024)     // TOKENS*D
#define XDB    (1024*96)       // TOKENS*96
#define LQN    77
#define MH     308             // B*LQ
#define OUTF   768

#define BKK 16
#define BNN 64

// ---------------- scratch buffers (no runtime allocation allowed) ----------------
__device__ float g_res [BLD];
__device__ float g_h   [2*BLD];     // split-K partials h0 | h1
__device__ float g_hn  [BLD];
__device__ float g_xz  [4*BLD];     // [tok][4096]: dir0 x|z, dir1 x|z
__device__ float g_xc  [2*BLD];     // conv+silu output per dir
__device__ float g_dt  [2*BLD];
__device__ float g_xdbl[2*XDB];     // [dir][tok][96]
__device__ float g_yp  [2*BLD];     // [tok][2048]: dir0 | dir1 (for split-K out-GEMM)
__device__ float g_kv  [2*BLD];     // [tok][2048]
__device__ float g_o   [MH*1024];
__device__ float g_po  [MH*1024];
__device__ float g_s1  [MH*1536];

// ---------------- helpers ----------------
__device__ __forceinline__ unsigned long long f2pack(float x, float y){
    unsigned long long r;
    asm("mov.b64 %0, {%1, %2};" : "=l"(r) : "f"(x), "f"(y));
    return r;
}
__device__ __forceinline__ void f2unpack(float& x, float& y, unsigned long long p){
    asm("mov.b64 {%0, %1}, %2;" : "=f"(x), "=f"(y) : "l"(p));
}
__device__ __forceinline__ void f2fma(unsigned long long& d, unsigned long long a, unsigned long long b){
    asm("fma.rn.f32x2 %0, %1, %2, %0;" : "+l"(d) : "l"(a), "l"(b));
}
__device__ __forceinline__ float siluf(float v){ return v / (1.f + __expf(-v)); }
__device__ __forceinline__ float softplusf(float v){ return v > 20.f ? v : log1pf(__expf(v)); }

__device__ __forceinline__ float block_sum(float v, float* red){
    #pragma unroll
    for (int o = 16; o; o >>= 1) v += __shfl_xor_sync(0xffffffffu, v, o);
    int w = threadIdx.x >> 5, ln = threadIdx.x & 31;
    if (ln == 0) red[w] = v;
    __syncthreads();
    float t = (threadIdx.x < 8) ? red[threadIdx.x] : 0.f;
    #pragma unroll
    for (int o = 4; o; o >>= 1) t += __shfl_xor_sync(0xffffffffu, t, o);
    if (threadIdx.x == 0) red[0] = t;
    __syncthreads();
    t = red[0];
    __syncthreads();
    return t;
}
__device__ __forceinline__ float block_max(float v, float* red){
    #pragma unroll
    for (int o = 16; o; o >>= 1) v = fmaxf(v, __shfl_xor_sync(0xffffffffu, v, o));
    int w = threadIdx.x >> 5, ln = threadIdx.x & 31;
    if (ln == 0) red[w] = v;
    __syncthreads();
    float t = (threadIdx.x < 8) ? red[threadIdx.x] : -3.0e38f;
    #pragma unroll
    for (int o = 4; o; o >>= 1) t = fmaxf(t, __shfl_xor_sync(0xffffffffu, t, o));
    if (threadIdx.x == 0) red[0] = t;
    __syncthreads();
    t = red[0];
    __syncthreads();
    return t;
}

// ================= BIG GEMM: 128x128 tile, duplicated-B smem, FFMA2 =================
// C[M,N] = act(A[M,K] @ W[N,K]^T + bias). Requires M%128==0, N%128==0, K%16==0,
// lda/ldw rows 16B-aligned. blockIdx.z strides sA/sW/sB/sC (element offsets).
// Per k-step per thread: 32 FFMA2 (64 MACs) + 12 conflict-free LDS.64, no packs.
template<int DOBIAS, int ACT>
__global__ void __launch_bounds__(256, 2) gemmT_k(
    const float* __restrict__ A, int lda, long long sA,
    const float* __restrict__ W, int ldw, long long sW,
    const float* __restrict__ bias, long long sB,
    float* __restrict__ C, int ldc, long long sC,
    int K)
{
    __shared__ __align__(16) float As[16][132];   // [k][m]
    __shared__ __align__(16) float Wd[16][288];   // [k][dup-n, padded every 16 floats]

    if (sA) A += (size_t)blockIdx.z * sA;
    if (sW) W += (size_t)blockIdx.z * sW;
    if (sC) C += (size_t)blockIdx.z * sC;
    if (DOBIAS && sB) bias += (size_t)blockIdx.z * sB;

    const int tid = threadIdx.x;
    const int tx  = tid & 15;
    const int ty  = tid >> 4;
    const int bm  = blockIdx.y * 128;
    const int bn  = blockIdx.x * 128;

    unsigned long long acc[4][8];
    #pragma unroll
    for (int p = 0; p < 4; ++p)
        #pragma unroll
        for (int j = 0; j < 8; ++j) acc[p][j] = 0ull;

    const int fA_r  = tid >> 2;            // 0..63 (first half), +64 second
    const int fA_kc = (tid & 3) * 4;

    for (int k0 = 0; k0 < K; k0 += 16) {
        // ---- A tile (transposed into As[k][m]), 2 x float4 per thread ----
        #pragma unroll
        for (int h2 = 0; h2 < 2; ++h2) {
            int r = fA_r + h2 * 64;
            float4 av = *(const float4*)(A + (size_t)(bm + r) * lda + k0 + fA_kc);
            As[fA_kc + 0][r] = av.x; As[fA_kc + 1][r] = av.y;
            As[fA_kc + 2][r] = av.z; As[fA_kc + 3][r] = av.w;
        }
        // ---- W tile, each value duplicated as an (w,w) 8B pair ----
        #pragma unroll
        for (int h2 = 0; h2 < 2; ++h2) {
            int wn = fA_r + h2 * 64;
            float4 wv = *(const float4*)(W + (size_t)(bn + wn) * ldw + k0 + fA_kc);
            int ph = 2 * wn + ((wn >> 3) << 1);     // phys(2*wn), 8B aligned
            *(float2*)&Wd[fA_kc + 0][ph] = make_float2(wv.x, wv.x);
            *(float2*)&Wd[fA_kc + 1][ph] = make_float2(wv.y, wv.y);
            *(float2*)&Wd[fA_kc + 2][ph] = make_float2(wv.z, wv.z);
            *(float2*)&Wd[fA_kc + 3][ph] = make_float2(wv.w, wv.w);
        }
        __syncthreads();

        #pragma unroll
        for (int kk = 0; kk < 16; ++kk) {
            unsigned long long av[4], bv[8];
            #pragma unroll
            for (int p = 0; p < 4; ++p)
                av[p] = *(const unsigned long long*)&As[kk][ty * 8 + 2 * p];
            #pragma unroll
            for (int j = 0; j < 8; ++j)
                bv[j] = *(const unsigned long long*)&Wd[kk][tx * 18 + 2 * j];
            #pragma unroll
            for (int p = 0; p < 4; ++p)
                #pragma unroll
                for (int j = 0; j < 8; ++j)
                    f2fma(acc[p][j], av[p], bv[j]);
        }
        __syncthreads();
    }

    // ---- epilogue: vectorized float4 stores (rows m0, m0+1; 8 contiguous cols) ----
    float bz[8];
    #pragma unroll
    for (int j = 0; j < 8; ++j) bz[j] = DOBIAS ? bias[bn + tx * 8 + j] : 0.f;

    #pragma unroll
    for (int p = 0; p < 4; ++p) {
        float r0[8], r1[8];
        #pragma unroll
        for (int j = 0; j < 8; ++j) {
            float x0, x1;
            f2unpack(x0, x1, acc[p][j]);
            x0 += bz[j]; x1 += bz[j];
            if (ACT == 1)      { x0 = siluf(x0);     x1 = siluf(x1); }
            else if (ACT == 2) { x0 = softplusf(x0); x1 = softplusf(x1); }
            r0[j] = x0; r1[j] = x1;
        }
        int m0 = bm + ty * 8 + 2 * p;
        float* c0 = C + (size_t)m0 * ldc + bn + tx * 8;
        float* c1 = c0 + ldc;
        *(float4*)(c0 + 0) = make_float4(r0[0], r0[1], r0[2], r0[3]);
        *(float4*)(c0 + 4) = make_float4(r0[4], r0[5], r0[6], r0[7]);
        *(float4*)(c1 + 0) = make_float4(r1[0], r1[1], r1[2], r1[3]);
        *(float4*)(c1 + 4) = make_float4(r1[4], r1[5], r1[6], r1[7]);
    }
}

// ================= skinny GEMM (kept from R5): BM=32, BN=64 =================
template<int BMT, int DOBIAS, int ACT, int SPLIT>
__global__ void __launch_bounds__(256) gemm_k(
    const float* __restrict__ A, int lda, long long sA,
    const float* __restrict__ W, int ldw, long long sW,
    const float* __restrict__ bias, long long sB,
    float* __restrict__ C, int ldc, long long sC,
    int M, int N, int K)
{
    constexpr int MP = BMT / 32;
    __shared__ __align__(16) float As[BKK][BMT + 4];
    __shared__ __align__(16) float Ws[BKK][BNN + 2];

    if (sA) A += (size_t)blockIdx.z * sA;
    if (sW) W += (size_t)blockIdx.z * sW;
    if (sC) C += (size_t)blockIdx.z * sC;
    if (DOBIAS && sB) bias += (size_t)blockIdx.z * sB;

    const int tid  = threadIdx.x;
    const int tx   = tid & 15;
    const int ty   = tid >> 4;
    const int bm   = blockIdx.y * BMT;
    const int bn   = blockIdx.x * BNN;
    const int kcol = (tid & 3) * 4;
    const int tyB  = ty * (BMT / 16);
    const int tx4  = tx * 4;

    unsigned long long acc[MP][4];
    #pragma unroll
    for (int p = 0; p < MP; ++p)
        #pragma unroll
        for (int j = 0; j < 4; ++j) acc[p][j] = 0ull;

    for (int k0 = 0; k0 < K; k0 += BKK) {
        #pragma unroll
        for (int h = 0; h < (BMT * 4 + 255) / 256; ++h) {
            int f = tid + h * 256;
            if (f < BMT * 4) {
                int r  = f >> 2;
                int kc = (f & 3) * 4;
                int m  = bm + r;
                float4 av = make_float4(0.f, 0.f, 0.f, 0.f);
                if (m < M) av = *(const float4*)(A + (size_t)m * lda + k0 + kc);
                As[kc + 0][r] = av.x; As[kc + 1][r] = av.y;
                As[kc + 2][r] = av.z; As[kc + 3][r] = av.w;
            }
        }
        {
            int wn = tid >> 2;
            int n  = bn + wn;
            float4 wv = make_float4(0.f, 0.f, 0.f, 0.f);
            if (n < N) wv = *(const float4*)(W + (size_t)n * ldw + k0 + kcol);
            int np = wn + ((wn >> 5) << 1);
            Ws[kcol + 0][np] = wv.x; Ws[kcol + 1][np] = wv.y;
            Ws[kcol + 2][np] = wv.z; Ws[kcol + 3][np] = wv.w;
        }
        __syncthreads();

        #pragma unroll
        for (int kk = 0; kk < BKK; ++kk) {
            unsigned long long av[MP];
            #pragma unroll
            for (int p = 0; p < MP; ++p)
                av[p] = *(const unsigned long long*)&As[kk][tyB + 2 * p];
            #pragma unroll
            for (int j = 0; j < 4; ++j) {
                int nb = tx4 + j;
                float bvv = Ws[kk][nb + ((nb >> 5) << 1)];
                unsigned long long bb = f2pack(bvv, bvv);
                #pragma unroll
                for (int p = 0; p < MP; ++p) f2fma(acc[p][j], av[p], bb);
            }
        }
        __syncthreads();
    }

    #pragma unroll
    for (int p = 0; p < MP; ++p) {
        #pragma unroll
        for (int j = 0; j < 4; ++j) {
            float x0, x1;
            f2unpack(x0, x1, acc[p][j]);
            int col = bn + tx4 + j;
            int m0  = bm + tyB + 2 * p;
            if (col < N) {
                float bz = DOBIAS ? bias[col] : 0.f;
                float r0 = x0 + bz, r1 = x1 + bz;
                if (ACT == 1)      { r0 = siluf(r0);     r1 = siluf(r1); }
                else if (ACT == 2) { r0 = softplusf(r0); r1 = softplusf(r1); }
                if (SPLIT) {
                    if (m0 < M) {
                        if (col < OUTF) C[(size_t)m0 * OUTF + col] = r0;
                        else            C[(size_t)MH * OUTF + (size_t)m0 * OUTF + (col - OUTF)] = r0;
                    }
                    if (m0 + 1 < M) {
                        if (col < OUTF) C[(size_t)(m0 + 1) * OUTF + col] = r1;
                        else            C[(size_t)MH * OUTF + (size_t)(m0 + 1) * OUTF + (col - OUTF)] = r1;
                    }
                } else {
                    if (m0 < M)     C[(size_t)m0 * ldc + col]       = r0;
                    if (m0 + 1 < M) C[(size_t)(m0 + 1) * ldc + col] = r1;
                }
            }
        }
    }
}

// ---------------- residual-add(s) + LayerNorm(*w) ----------------
__global__ void __launch_bounds__(256) ln_k(const float* __restrict__ add0,
                                            const float* __restrict__ add1,
                                            float* __restrict__ res,
                                            const float* __restrict__ w,
                                            float* __restrict__ out)
{
    __shared__ float red[8];
    int t = blockIdx.x;
    size_t base = (size_t)t * DDIM;
    int tid = threadIdx.x;
    float v[4];
    #pragma unroll
    for (int j = 0; j < 4; ++j) {
        int d = j * 256 + tid;
        float r = res[base + d];
        if (add0) { r += add0[base + d] + add1[base + d]; res[base + d] = r; }
        v[j] = r;
    }
    float s = v[0] + v[1] + v[2] + v[3];
    s = block_sum(s, red);
    float mean = s * (1.f / DDIM);
    float q = 0.f;
    #pragma unroll
    for (int j = 0; j < 4; ++j) { float d0 = v[j] - mean; q += d0 * d0; }
    q = block_sum(q, red);
    float inv = rsqrtf(q * (1.f / DDIM) + 1e-5f);
    #pragma unroll
    for (int j = 0; j < 4; ++j) {
        int d = j * 256 + tid;
        out[base + d] = (v[j] - mean) * inv * w[d];
    }
}

// ---------------- depthwise conv (dir0 causal, dir1 anti-causal) + bias + silu ----------------
__global__ void __launch_bounds__(256) conv_k(const float* __restrict__ cw,
                                              const float* __restrict__ cb,
                                              int layer)
{
    int g = blockIdx.x * 256 + threadIdx.x;
    int tok = g >> 10, d = g & 1023;
    int b = tok >> 8, t = tok & 255;
    const float* xz_b = g_xz + (size_t)b * 256 * 4096;
    {
        const float* w = cw + ((size_t)(layer * 2 + 0) * 1024 + d) * 4;
        float a = cb[(size_t)(layer * 2 + 0) * 1024 + d];
        #pragma unroll
        for (int j = 0; j < 4; ++j) {
            int ts = t - 3 + j;
            if (ts >= 0) a = fmaf(w[j], xz_b[(size_t)ts * 4096 + d], a);
        }
        g_xc[(size_t)tok * 1024 + d] = siluf(a);
    }
    {
        const float* w = cw + ((size_t)(layer * 2 + 1) * 1024 + d) * 4;
        float a = cb[(size_t)(layer * 2 + 1) * 1024 + d];
        #pragma unroll
        for (int j = 0; j < 4; ++j) {
            int ts = t + 3 - j;
            if (ts <= 255) a = fmaf(w[j], xz_b[(size_t)ts * 4096 + 2048 + d], a);
        }
        g_xc[(size_t)BLD + (size_t)tok * 1024 + d] = siluf(a);
    }
}

// ---------------- selective scan with next-step prefetch ----------------
__global__ void __launch_bounds__(64) scan_k(const float* __restrict__ A_log,
                                             const float* __restrict__ D_p,
                                             int layer)
{
    int dir = blockIdx.z, b = blockIdx.y;
    int d = blockIdx.x * 64 + threadIdx.x;
    size_t pbase = (size_t)((layer * 2 + dir) * 1024 + d);
    float Ar[16];
    const float* al = A_log + pbase * 16;
    #pragma unroll
    for (int n = 0; n < 16; ++n) Ar[n] = -__expf(al[n]);
    float Dp = D_p[pbase];
    float h[16];
    #pragma unroll
    for (int n = 0; n < 16; ++n) h[n] = 0.f;

    const float* dt_p = g_dt + (size_t)dir * BLD + (size_t)b * 256 * 1024 + d;
    const float* x_p  = g_xc + (size_t)dir * BLD + (size_t)b * 256 * 1024 + d;
    const float* z_p  = g_xz + (size_t)b * 256 * 4096 + dir * 2048 + 1024 + d;
    const float* bc   = g_xdbl + (size_t)dir * XDB + (size_t)b * 256 * 96;
    float* y_p = g_yp + (size_t)b * 256 * 2048 + dir * 1024 + d;

    int t   = dir ? 255 : 0;
    int stp = dir ? -1 : 1;

    float dt_c = dt_p[(size_t)t * 1024];
    float xv_c = x_p [(size_t)t * 1024];
    float zv_c = z_p [(size_t)t * 4096];
    float4 Bq[4], Cq[4];
    {
        const float4* xv4 = (const float4*)(bc + t * 96 + 64);
        #pragma unroll
        for (int qk = 0; qk < 4; ++qk) { Bq[qk] = xv4[qk]; Cq[qk] = xv4[qk + 4]; }
    }

    for (int s = 0; s < 256; ++s) {
        int tn = t + stp;
        float dt_nv = 0.f, xv_n = 0.f, zv_n = 0.f;
        float4 Bn[4], Cn[4];
        if (s < 255) {
            dt_nv = dt_p[(size_t)tn * 1024];
            xv_n  = x_p [(size_t)tn * 1024];
            zv_n  = z_p [(size_t)tn * 4096];
            const float4* xv4 = (const float4*)(bc + tn * 96 + 64);
            #pragma unroll
            for (int qk = 0; qk < 4; ++qk) { Bn[qk] = xv4[qk]; Cn[qk] = xv4[qk + 4]; }
        }

        float Bf[16], Cf[16];
        #pragma unroll
        for (int qk = 0; qk < 4; ++qk) {
            Bf[qk*4+0] = Bq[qk].x; Bf[qk*4+1] = Bq[qk].y; Bf[qk*4+2] = Bq[qk].z; Bf[qk*4+3] = Bq[qk].w;
            Cf[qk*4+0] = Cq[qk].x; Cf[qk*4+1] = Cq[qk].y; Cf[qk*4+2] = Cq[qk].z; Cf[qk*4+3] = Cq[qk].w;
        }

        float dx = dt_c * xv_c;
        float y = 0.f;
        #pragma unroll
        for (int n = 0; n < 16; ++n) {
            float wv = __expf(dt_c * Ar[n]);
            h[n] = fmaf(wv, h[n], dx * Bf[n]);
            y = fmaf(h[n], Cf[n], y);
        }
        y = fmaf(xv_c, Dp, y);
        y_p[(size_t)t * 2048] = y * siluf(zv_c);

        t = tn; dt_c = dt_nv; xv_c = xv_n; zv_c = zv_n;
        #pragma unroll
        for (int qk = 0; qk < 4; ++qk) { Bq[qk] = Bn[qk]; Cq[qk] = Cn[qk]; }
    }
}

// ---------------- cross-attention: one block per (qi, head, batch) ----------------
__global__ void __launch_bounds__(256) attn_k(const float* __restrict__ q)
{
    __shared__ float qs[64];
    __shared__ float sc[256];
    __shared__ float po[4][64];
    __shared__ float red[8];
    int qi = blockIdx.x, hh = blockIdx.y, b = blockIdx.z;
    int tid = threadIdx.x;
    if (tid < 64) qs[tid] = q[((size_t)hh * LQN + qi) * 64 + tid];
    __syncthreads();
    float s;
    {
        const float* kp = g_kv + ((size_t)(b * 256 + tid)) * 2048 + hh * 128;
        float a = 0.f;
        #pragma unroll 8
        for (int d0 = 0; d0 < 64; ++d0) a = fmaf(qs[d0], kp[d0], a);
        s = a * 0.125f;
    }
    float mx = block_max(s, red);
    float e  = __expf(s - mx);
    float Z  = block_sum(e, red);
    sc[tid] = e / Z;
    __syncthreads();
    int d0 = tid & 63, tq = tid >> 6;
    float a = 0.f;
    const float* vb = g_kv + ((size_t)(b * 256 + tq * 64)) * 2048 + hh * 128 + 64 + d0;
    for (int tt = 0; tt < 64; ++tt) a = fmaf(sc[tq * 64 + tt], vb[(size_t)tt * 2048], a);
    po[tq][d0] = a;
    __syncthreads();
    if (tid < 64) {
        float o = po[0][tid] + po[1][tid] + po[2][tid] + po[3][tid];
        g_o[((size_t)b * LQN + qi) * 1024 + hh * 64 + tid] = o;
    }
}

// ---------------- host-side launch helpers ----------------
template<int DOBIAS, int ACT>
static void gemmT(const float* A, int lda, long long sA,
                  const float* W, int ldw, long long sW,
                  const float* bias, long long sB,
                  float* C, int ldc, long long sC,
                  int M, int N, int K, int nz)
{
    dim3 grid(N / 128, M / 128, nz);
    gemmT_k<DOBIAS, ACT><<<grid, 256>>>(A, lda, sA, W, ldw, sW, bias, sB, C, ldc, sC, K);
}

template<int BMT, int DOBIAS, int ACT, int SPLIT>
static void gemm(const float* A, int lda, long long sA,
                 const float* W, int ldw, long long sW,
                 const float* bias, long long sB,
                 float* C, int ldc, long long sC,
                 int M, int N, int K, int nz)
{
    dim3 grid((N + BNN - 1) / BNN, (M + BMT - 1) / BMT, nz);
    gemm_k<BMT, DOBIAS, ACT, SPLIT><<<grid, 256>>>(A, lda, sA, W, ldw, sW,
                                                   bias, sB, C, ldc, sC, M, N, K);
}

extern "C" void kernel_launch(void* const* d_in, const int* in_sizes, int n_in,
                              void* d_out, int out_size)
{
    (void)in_sizes; (void)n_in; (void)out_size;
    const float* x       = (const float*)d_in[0];
    const float* stem_W  = (const float*)d_in[1];
    const float* stem_b  = (const float*)d_in[2];
    const float* norm_w  = (const float*)d_in[3];
    const float* in_W    = (const float*)d_in[4];
    const float* conv_w  = (const float*)d_in[5];
    const float* conv_b  = (const float*)d_in[6];
    const float* xproj_W = (const float*)d_in[7];
    const float* dt_W    = (const float*)d_in[8];
    const float* dt_b    = (const float*)d_in[9];
    const float* A_log   = (const float*)d_in[10];
    const float* D_p     = (const float*)d_in[11];
    const float* out_W   = (const float*)d_in[12];
    const float* q       = (const float*)d_in[13];
    const float* kv_W    = (const float*)d_in[14];
    const float* po_W    = (const float*)d_in[15];
    const float* po_b    = (const float*)d_in[16];
    const float* h1_W    = (const float*)d_in[17];
    const float* h1_b    = (const float*)d_in[18];
    const float* h2_W    = (const float*)d_in[19];
    const float* h2_b    = (const float*)d_in[20];
    float* out = (float*)d_out;

    float *p_res, *p_h, *p_hn, *p_xz, *p_xc, *p_dt, *p_xdbl, *p_yp, *p_kv, *p_o, *p_po, *p_s1;
    cudaGetSymbolAddress((void**)&p_res,  g_res);
    cudaGetSymbolAddress((void**)&p_h,    g_h);
    cudaGetSymbolAddress((void**)&p_hn,   g_hn);
    cudaGetSymbolAddress((void**)&p_xz,   g_xz);
    cudaGetSymbolAddress((void**)&p_xc,   g_xc);
    cudaGetSymbolAddress((void**)&p_dt,   g_dt);
    cudaGetSymbolAddress((void**)&p_xdbl, g_xdbl);
    cudaGetSymbolAddress((void**)&p_yp,   g_yp);
    cudaGetSymbolAddress((void**)&p_kv,   g_kv);
    cudaGetSymbolAddress((void**)&p_o,    g_o);
    cudaGetSymbolAddress((void**)&p_po,   g_po);
    cudaGetSymbolAddress((void**)&p_s1,   g_s1);

    // stem: res = x @ stem_W^T + stem_b      (M=1024, N=1024, K=64)
    gemmT<1,0>(x, 64, 0, stem_W, 64, 0, stem_b, 0,
               p_res, 1024, 0, TOKENS, 1024, 64, 1);

    for (int i = 0; i < 16; ++i) {
        // res += h0 + h1 (i>0); hn = LN(res)*norm_w[i]
        ln_k<<<TOKENS, 256>>>(i == 0 ? nullptr : p_h,
                              i == 0 ? nullptr : p_h + BLD,
                              p_res, norm_w + (size_t)i * 1024, p_hn);
        // xz (both dirs fused): N=4096
        gemmT<0,0>(p_hn, 1024, 0, in_W + (size_t)i * 4096 * 1024, 1024, 0,
                   nullptr, 0, p_xz, 4096, 0, TOKENS, 4096, 1024, 1);
        // depthwise conv + silu (both dirs)
        conv_k<<<4096, 256>>>(conv_w, conv_b, i);
        // xproj: N=96, dirs via blockIdx.z (skinny kernel)
        gemm<32,0,0,0>(p_xc, 1024, BLD,
                       xproj_W + (size_t)i * 2 * 96 * 1024, 1024, (long long)96 * 1024,
                       nullptr, 0, p_xdbl, 96, XDB, TOKENS, 96, 1024, 2);
        // dt = softplus(xdbl[:, :64] @ dt_W^T + dt_b): K=64, dirs via z
        gemmT<1,2>(p_xdbl, 96, XDB,
                   dt_W + (size_t)i * 2 * 1024 * 64, 64, (long long)1024 * 64,
                   dt_b + (size_t)i * 2 * 1024, 1024,
                   p_dt, 1024, BLD, TOKENS, 1024, 64, 2);
        // selective scan (+x*Dp, *silu(z)) -> interleaved yp
        scan_k<<<dim3(16, 4, 2), 64>>>(A_log, D_p, i);
        // h0/h1 = yp[:, dir*1024 : ] @ out_W[i,dir]^T (split-K over dirs via z)
        gemmT<0,0>(p_yp, 2048, 1024,
                   out_W + (size_t)i * 2 * 1024 * 1024, 1024, (long long)1024 * 1024,
                   nullptr, 0, p_h, 1024, BLD, TOKENS, 1024, 1024, 2);
    }

    // final residual + LN
    ln_k<<<TOKENS, 256>>>(p_h, p_h + BLD, p_res, norm_w + (size_t)16 * 1024, p_hn);
    // kv projection: N=2048
    gemmT<0,0>(p_hn, 1024, 0, kv_W, 1024, 0, nullptr, 0,
               p_kv, 2048, 0, TOKENS, 2048, 1024, 1);
    // attention
    attn_k<<<dim3(LQN, 16, 4), 256>>>(q);
    // s = silu(o @ po_W^T + po_b)
    gemm<32,1,1,0>(p_o, 1024, 0, po_W, 1024, 0, po_b, 0,
                   p_po, 1024, 0, MH, 1024, 1024, 1);
    // s1 = silu(s @ h1_W^T + h1_b)
    gemm<32,1,1,0>(p_po, 1024, 0, h1_W, 1024, 0, h1_b, 0,
                   p_s1, 1536, 0, MH, 1536, 1024, 1);
    // s2 = s1 @ h2_W^T + h2_b, split-written as (a | b) into d_out
    gemm<32,1,0,1>(p_s1, 1536, 0, h2_W, 1536, 0, h2_b, 0,
                   out, 0, 0, MH, 1536, 1536, 1);
}

// round 8
// speedup vs baseline: 1.4194x; 1.0666x over previous
#include <cuda_runtime.h>
#include <cuda_bf16.h>
#include <cstdint>

// ---------------- problem constants ----------------
#define LLEN   256
#define DDIM   1024
#define TOKENS 1024            // B*L
#define BLD    (1024*1024)     // TOKENS*D
#define XDB    (1024*96)       // TOKENS*96
#define LQN    77
#define MH     308             // B*LQ
#define MHP    384             // MH padded to 3*128 for gemmT
#define OUTF   768

#define BKK 16
#define BNN 64

// ---------------- scratch buffers (no runtime allocation allowed) ----------------
__device__ float g_res [BLD];
__device__ float g_h   [2*BLD];     // split-K partials h0 | h1
__device__ float g_hn  [BLD];
__device__ float g_xz  [4*BLD];     // [tok][4096]: dir0 x|z, dir1 x|z
__device__ float g_xc  [2*BLD];     // conv+silu output per dir
__device__ float g_dt  [2*BLD];
__device__ float g_xdbl[2*XDB];     // [dir][tok][96]
__device__ float g_yp  [2*BLD];     // [tok][2048]: dir0 | dir1
__device__ float g_kv  [2*BLD];     // [tok][2048]
__device__ float g_o   [MHP*1024];  // rows >= MH stay zero
__device__ float g_po  [MHP*1024];
__device__ float g_s1  [MHP*1536];

// ---------------- helpers ----------------
__device__ __forceinline__ unsigned long long f2pack(float x, float y){
    unsigned long long r;
    asm("mov.b64 %0, {%1, %2};" : "=l"(r) : "f"(x), "f"(y));
    return r;
}
__device__ __forceinline__ void f2unpack(float& x, float& y, unsigned long long p){
    asm("mov.b64 {%0, %1}, %2;" : "=f"(x), "=f"(y) : "l"(p));
}
__device__ __forceinline__ void f2fma(unsigned long long& d, unsigned long long a, unsigned long long b){
    asm("fma.rn.f32x2 %0, %1, %2, %0;" : "+l"(d) : "l"(a), "l"(b));
}
__device__ __forceinline__ float siluf(float v){ return v / (1.f + __expf(-v)); }
__device__ __forceinline__ float softplusf(float v){ return v > 20.f ? v : log1pf(__expf(v)); }

__device__ __forceinline__ float block_sum(float v, float* red){
    #pragma unroll
    for (int o = 16; o; o >>= 1) v += __shfl_xor_sync(0xffffffffu, v, o);
    int w = threadIdx.x >> 5, ln = threadIdx.x & 31;
    if (ln == 0) red[w] = v;
    __syncthreads();
    float t = (threadIdx.x < 8) ? red[threadIdx.x] : 0.f;
    #pragma unroll
    for (int o = 4; o; o >>= 1) t += __shfl_xor_sync(0xffffffffu, t, o);
    if (threadIdx.x == 0) red[0] = t;
    __syncthreads();
    t = red[0];
    __syncthreads();
    return t;
}
__device__ __forceinline__ float block_max(float v, float* red){
    #pragma unroll
    for (int o = 16; o; o >>= 1) v = fmaxf(v, __shfl_xor_sync(0xffffffffu, v, o));
    int w = threadIdx.x >> 5, ln = threadIdx.x & 31;
    if (ln == 0) red[w] = v;
    __syncthreads();
    float t = (threadIdx.x < 8) ? red[threadIdx.x] : -3.0e38f;
    #pragma unroll
    for (int o = 4; o; o >>= 1) t = fmaxf(t, __shfl_xor_sync(0xffffffffu, t, o));
    if (threadIdx.x == 0) red[0] = t;
    __syncthreads();
    t = red[0];
    __syncthreads();
    return t;
}

// ================= BIG GEMM: 128x128 tile, duplicated-B smem, FFMA2, pipelined =================
// C[M,N] = act(A[M,K] @ W[N,K]^T + bias). M%128==0, N%128==0, K%16==0, rows 16B-aligned.
// Register-prefetch software pipeline: LDG for tile k+1 overlaps FFMA2 compute on tile k.
// SPLIT==1: final-output epilogue (guard m<MH, split cols at OUTF into two planes).
template<int DOBIAS, int ACT, int SPLIT>
__global__ void __launch_bounds__(256, 2) gemmT_k(
    const float* __restrict__ A, int lda, long long sA,
    const float* __restrict__ W, int ldw, long long sW,
    const float* __restrict__ bias, long long sB,
    float* __restrict__ C, int ldc, long long sC,
    int K)
{
    __shared__ __align__(16) float As[16][132];   // [k][m]
    __shared__ __align__(16) float Wd[16][290];   // [k][dup-n], stride 290 to soften STS conflicts

    if (sA) A += (size_t)blockIdx.z * sA;
    if (sW) W += (size_t)blockIdx.z * sW;
    if (sC) C += (size_t)blockIdx.z * sC;
    if (DOBIAS && sB) bias += (size_t)blockIdx.z * sB;

    const int tid = threadIdx.x;
    const int tx  = tid & 15;
    const int ty  = tid >> 4;
    const int bm  = blockIdx.y * 128;
    const int bn  = blockIdx.x * 128;

    unsigned long long acc[4][8];
    #pragma unroll
    for (int p = 0; p < 4; ++p)
        #pragma unroll
        for (int j = 0; j < 8; ++j) acc[p][j] = 0ull;

    const int fA_r  = tid >> 2;            // 0..63 (first half), +64 second
    const int fA_kc = (tid & 3) * 4;
    const float* Abase = A + (size_t)(bm + fA_r) * lda + fA_kc;
    const float* Wbase = W + (size_t)(bn + fA_r) * ldw + fA_kc;

    float4 pa[2], pw[2];
    #pragma unroll
    for (int h2 = 0; h2 < 2; ++h2) {
        pa[h2] = *(const float4*)(Abase + (size_t)h2 * 64 * lda);
        pw[h2] = *(const float4*)(Wbase + (size_t)h2 * 64 * ldw);
    }

    for (int k0 = 0; k0 < K; k0 += 16) {
        // ---- store current prefetch regs into smem ----
        #pragma unroll
        for (int h2 = 0; h2 < 2; ++h2) {
            int r = fA_r + h2 * 64;
            As[fA_kc + 0][r] = pa[h2].x; As[fA_kc + 1][r] = pa[h2].y;
            As[fA_kc + 2][r] = pa[h2].z; As[fA_kc + 3][r] = pa[h2].w;
            int ph = 2 * r + ((r >> 3) << 1);
            *(float2*)&Wd[fA_kc + 0][ph] = make_float2(pw[h2].x, pw[h2].x);
            *(float2*)&Wd[fA_kc + 1][ph] = make_float2(pw[h2].y, pw[h2].y);
            *(float2*)&Wd[fA_kc + 2][ph] = make_float2(pw[h2].z, pw[h2].z);
            *(float2*)&Wd[fA_kc + 3][ph] = make_float2(pw[h2].w, pw[h2].w);
        }
        __syncthreads();

        // ---- issue next tile's LDG (overlaps compute below) ----
        if (k0 + 16 < K) {
            #pragma unroll
            for (int h2 = 0; h2 < 2; ++h2) {
                pa[h2] = *(const float4*)(Abase + (size_t)h2 * 64 * lda + k0 + 16);
                pw[h2] = *(const float4*)(Wbase + (size_t)h2 * 64 * ldw + k0 + 16);
            }
        }

        // ---- FFMA2 compute on current smem tile ----
        #pragma unroll
        for (int kk = 0; kk < 16; ++kk) {
            unsigned long long av[4], bv[8];
            #pragma unroll
            for (int p = 0; p < 4; ++p)
                av[p] = *(const unsigned long long*)&As[kk][ty * 8 + 2 * p];
            #pragma unroll
            for (int j = 0; j < 8; ++j)
                bv[j] = *(const unsigned long long*)&Wd[kk][tx * 18 + 2 * j];
            #pragma unroll
            for (int p = 0; p < 4; ++p)
                #pragma unroll
                for (int j = 0; j < 8; ++j)
                    f2fma(acc[p][j], av[p], bv[j]);
        }
        __syncthreads();
    }

    // ---- epilogue ----
    float bz[8];
    #pragma unroll
    for (int j = 0; j < 8; ++j) bz[j] = DOBIAS ? bias[bn + tx * 8 + j] : 0.f;

    #pragma unroll
    for (int p = 0; p < 4; ++p) {
        float r0[8], r1[8];
        #pragma unroll
        for (int j = 0; j < 8; ++j) {
            float x0, x1;
            f2unpack(x0, x1, acc[p][j]);
            x0 += bz[j]; x1 += bz[j];
            if (ACT == 1)      { x0 = siluf(x0);     x1 = siluf(x1); }
            else if (ACT == 2) { x0 = softplusf(x0); x1 = softplusf(x1); }
            r0[j] = x0; r1[j] = x1;
        }
        int m0 = bm + ty * 8 + 2 * p;
        int cb = bn + tx * 8;
        if (SPLIT) {
            // out layout: a = s[:, :768] then b = s[:, 768:], each [MH][768]
            float* o0 = (cb < OUTF) ? (C + (size_t)m0 * OUTF + cb)
                                    : (C + (size_t)MH * OUTF + (size_t)m0 * OUTF + (cb - OUTF));
            if (m0 < MH) {
                *(float4*)(o0 + 0) = make_float4(r0[0], r0[1], r0[2], r0[3]);
                *(float4*)(o0 + 4) = make_float4(r0[4], r0[5], r0[6], r0[7]);
            }
            if (m0 + 1 < MH) {
                float* o1 = o0 + OUTF;
                *(float4*)(o1 + 0) = make_float4(r1[0], r1[1], r1[2], r1[3]);
                *(float4*)(o1 + 4) = make_float4(r1[4], r1[5], r1[6], r1[7]);
            }
        } else {
            float* c0 = C + (size_t)m0 * ldc + cb;
            float* c1 = c0 + ldc;
            *(float4*)(c0 + 0) = make_float4(r0[0], r0[1], r0[2], r0[3]);
            *(float4*)(c0 + 4) = make_float4(r0[4], r0[5], r0[6], r0[7]);
            *(float4*)(c1 + 0) = make_float4(r1[0], r1[1], r1[2], r1[3]);
            *(float4*)(c1 + 4) = make_float4(r1[4], r1[5], r1[6], r1[7]);
        }
    }
}

// ================= skinny GEMM (xproj only): BM=32, BN=64 =================
template<int BMT>
__global__ void __launch_bounds__(256) gemm_k(
    const float* __restrict__ A, int lda, long long sA,
    const float* __restrict__ W, int ldw, long long sW,
    float* __restrict__ C, int ldc, long long sC,
    int M, int N, int K)
{
    constexpr int MP = BMT / 32;
    __shared__ __align__(16) float As[BKK][BMT + 4];
    __shared__ __align__(16) float Ws[BKK][BNN + 2];

    if (sA) A += (size_t)blockIdx.z * sA;
    if (sW) W += (size_t)blockIdx.z * sW;
    if (sC) C += (size_t)blockIdx.z * sC;

    const int tid  = threadIdx.x;
    const int tx   = tid & 15;
    const int ty   = tid >> 4;
    const int bm   = blockIdx.y * BMT;
    const int bn   = blockIdx.x * BNN;
    const int kcol = (tid & 3) * 4;
    const int tyB  = ty * (BMT / 16);
    const int tx4  = tx * 4;

    unsigned long long acc[MP][4];
    #pragma unroll
    for (int p = 0; p < MP; ++p)
        #pragma unroll
        for (int j = 0; j < 4; ++j) acc[p][j] = 0ull;

    for (int k0 = 0; k0 < K; k0 += BKK) {
        #pragma unroll
        for (int h = 0; h < (BMT * 4 + 255) / 256; ++h) {
            int f = tid + h * 256;
            if (f < BMT * 4) {
                int r  = f >> 2;
                int kc = (f & 3) * 4;
                int m  = bm + r;
                float4 av = make_float4(0.f, 0.f, 0.f, 0.f);
                if (m < M) av = *(const float4*)(A + (size_t)m * lda + k0 + kc);
                As[kc + 0][r] = av.x; As[kc + 1][r] = av.y;
                As[kc + 2][r] = av.z; As[kc + 3][r] = av.w;
            }
        }
        {
            int wn = tid >> 2;
            int n  = bn + wn;
            float4 wv = make_float4(0.f, 0.f, 0.f, 0.f);
            if (n < N) wv = *(const float4*)(W + (size_t)n * ldw + k0 + kcol);
            int np = wn + ((wn >> 5) << 1);
            Ws[kcol + 0][np] = wv.x; Ws[kcol + 1][np] = wv.y;
            Ws[kcol + 2][np] = wv.z; Ws[kcol + 3][np] = wv.w;
        }
        __syncthreads();

        #pragma unroll
        for (int kk = 0; kk < BKK; ++kk) {
            unsigned long long av[MP];
            #pragma unroll
            for (int p = 0; p < MP; ++p)
                av[p] = *(const unsigned long long*)&As[kk][tyB + 2 * p];
            #pragma unroll
            for (int j = 0; j < 4; ++j) {
                int nb = tx4 + j;
                float bvv = Ws[kk][nb + ((nb >> 5) << 1)];
                unsigned long long bb = f2pack(bvv, bvv);
                #pragma unroll
                for (int p = 0; p < MP; ++p) f2fma(acc[p][j], av[p], bb);
            }
        }
        __syncthreads();
    }

    #pragma unroll
    for (int p = 0; p < MP; ++p) {
        #pragma unroll
        for (int j = 0; j < 4; ++j) {
            float x0, x1;
            f2unpack(x0, x1, acc[p][j]);
            int col = bn + tx4 + j;
            int m0  = bm + tyB + 2 * p;
            if (col < N) {
                if (m0 < M)     C[(size_t)m0 * ldc + col]       = x0;
                if (m0 + 1 < M) C[(size_t)(m0 + 1) * ldc + col] = x1;
            }
        }
    }
}

// ---------------- residual-add(s) + LayerNorm(*w) ----------------
__global__ void __launch_bounds__(256) ln_k(const float* __restrict__ add0,
                                            const float* __restrict__ add1,
                                            float* __restrict__ res,
                                            const float* __restrict__ w,
                                            float* __restrict__ out)
{
    __shared__ float red[8];
    int t = blockIdx.x;
    size_t base = (size_t)t * DDIM;
    int tid = threadIdx.x;
    float v[4];
    #pragma unroll
    for (int j = 0; j < 4; ++j) {
        int d = j * 256 + tid;
        float r = res[base + d];
        if (add0) { r += add0[base + d] + add1[base + d]; res[base + d] = r; }
        v[j] = r;
    }
    float s = v[0] + v[1] + v[2] + v[3];
    s = block_sum(s, red);
    float mean = s * (1.f / DDIM);
    float q = 0.f;
    #pragma unroll
    for (int j = 0; j < 4; ++j) { float d0 = v[j] - mean; q += d0 * d0; }
    q = block_sum(q, red);
    float inv = rsqrtf(q * (1.f / DDIM) + 1e-5f);
    #pragma unroll
    for (int j = 0; j < 4; ++j) {
        int d = j * 256 + tid;
        out[base + d] = (v[j] - mean) * inv * w[d];
    }
}

// ---------------- depthwise conv (dir0 causal, dir1 anti-causal) + bias + silu ----------------
__global__ void __launch_bounds__(256) conv_k(const float* __restrict__ cw,
                                              const float* __restrict__ cb,
                                              int layer)
{
    int g = blockIdx.x * 256 + threadIdx.x;
    int tok = g >> 10, d = g & 1023;
    int b = tok >> 8, t = tok & 255;
    const float* xz_b = g_xz + (size_t)b * 256 * 4096;
    {
        const float* w = cw + ((size_t)(layer * 2 + 0) * 1024 + d) * 4;
        float a = cb[(size_t)(layer * 2 + 0) * 1024 + d];
        #pragma unroll
        for (int j = 0; j < 4; ++j) {
            int ts = t - 3 + j;
            if (ts >= 0) a = fmaf(w[j], xz_b[(size_t)ts * 4096 + d], a);
        }
        g_xc[(size_t)tok * 1024 + d] = siluf(a);
    }
    {
        const float* w = cw + ((size_t)(layer * 2 + 1) * 1024 + d) * 4;
        float a = cb[(size_t)(layer * 2 + 1) * 1024 + d];
        #pragma unroll
        for (int j = 0; j < 4; ++j) {
            int ts = t + 3 - j;
            if (ts <= 255) a = fmaf(w[j], xz_b[(size_t)ts * 4096 + 2048 + d], a);
        }
        g_xc[(size_t)BLD + (size_t)tok * 1024 + d] = siluf(a);
    }
}

// ---------------- selective scan with next-step prefetch ----------------
__global__ void __launch_bounds__(64) scan_k(const float* __restrict__ A_log,
                                             const float* __restrict__ D_p,
                                             int layer)
{
    int dir = blockIdx.z, b = blockIdx.y;
    int d = blockIdx.x * 64 + threadIdx.x;
    size_t pbase = (size_t)((layer * 2 + dir) * 1024 + d);
    float Ar[16];
    const float* al = A_log + pbase * 16;
    #pragma unroll
    for (int n = 0; n < 16; ++n) Ar[n] = -__expf(al[n]);
    float Dp = D_p[pbase];
    float h[16];
    #pragma unroll
    for (int n = 0; n < 16; ++n) h[n] = 0.f;

    const float* dt_p = g_dt + (size_t)dir * BLD + (size_t)b * 256 * 1024 + d;
    const float* x_p  = g_xc + (size_t)dir * BLD + (size_t)b * 256 * 1024 + d;
    const float* z_p  = g_xz + (size_t)b * 256 * 4096 + dir * 2048 + 1024 + d;
    const float* bc   = g_xdbl + (size_t)dir * XDB + (size_t)b * 256 * 96;
    float* y_p = g_yp + (size_t)b * 256 * 2048 + dir * 1024 + d;

    int t   = dir ? 255 : 0;
    int stp = dir ? -1 : 1;

    float dt_c = dt_p[(size_t)t * 1024];
    float xv_c = x_p [(size_t)t * 1024];
    float zv_c = z_p [(size_t)t * 4096];
    float4 Bq[4], Cq[4];
    {
        const float4* xv4 = (const float4*)(bc + t * 96 + 64);
        #pragma unroll
        for (int qk = 0; qk < 4; ++qk) { Bq[qk] = xv4[qk]; Cq[qk] = xv4[qk + 4]; }
    }

    for (int s = 0; s < 256; ++s) {
        int tn = t + stp;
        float dt_nv = 0.f, xv_n = 0.f, zv_n = 0.f;
        float4 Bn[4], Cn[4];
        if (s < 255) {
            dt_nv = dt_p[(size_t)tn * 1024];
            xv_n  = x_p [(size_t)tn * 1024];
            zv_n  = z_p [(size_t)tn * 4096];
            const float4* xv4 = (const float4*)(bc + tn * 96 + 64);
            #pragma unroll
            for (int qk = 0; qk < 4; ++qk) { Bn[qk] = xv4[qk]; Cn[qk] = xv4[qk + 4]; }
        }

        float Bf[16], Cf[16];
        #pragma unroll
        for (int qk = 0; qk < 4; ++qk) {
            Bf[qk*4+0] = Bq[qk].x; Bf[qk*4+1] = Bq[qk].y; Bf[qk*4+2] = Bq[qk].z; Bf[qk*4+3] = Bq[qk].w;
            Cf[qk*4+0] = Cq[qk].x; Cf[qk*4+1] = Cq[qk].y; Cf[qk*4+2] = Cq[qk].z; Cf[qk*4+3] = Cq[qk].w;
        }

        float dx = dt_c * xv_c;
        float y = 0.f;
        #pragma unroll
        for (int n = 0; n < 16; ++n) {
            float wv = __expf(dt_c * Ar[n]);
            h[n] = fmaf(wv, h[n], dx * Bf[n]);
            y = fmaf(h[n], Cf[n], y);
        }
        y = fmaf(xv_c, Dp, y);
        y_p[(size_t)t * 2048] = y * siluf(zv_c);

        t = tn; dt_c = dt_nv; xv_c = xv_n; zv_c = zv_n;
        #pragma unroll
        for (int qk = 0; qk < 4; ++qk) { Bq[qk] = Bn[qk]; Cq[qk] = Cn[qk]; }
    }
}

// ---------------- cross-attention: one block per (qi, head, batch) ----------------
__global__ void __launch_bounds__(256) attn_k(const float* __restrict__ q)
{
    __shared__ float qs[64];
    __shared__ float sc[256];
    __shared__ float po[4][64];
    __shared__ float red[8];
    int qi = blockIdx.x, hh = blockIdx.y, b = blockIdx.z;
    int tid = threadIdx.x;
    if (tid < 64) qs[tid] = q[((size_t)hh * LQN + qi) * 64 + tid];
    __syncthreads();
    float s;
    {
        const float* kp = g_kv + ((size_t)(b * 256 + tid)) * 2048 + hh * 128;
        float a = 0.f;
        #pragma unroll 8
        for (int d0 = 0; d0 < 64; ++d0) a = fmaf(qs[d0], kp[d0], a);
        s = a * 0.125f;
    }
    float mx = block_max(s, red);
    float e  = __expf(s - mx);
    float Z  = block_sum(e, red);
    sc[tid] = e / Z;
    __syncthreads();
    int d0 = tid & 63, tq = tid >> 6;
    float a = 0.f;
    const float* vb = g_kv + ((size_t)(b * 256 + tq * 64)) * 2048 + hh * 128 + 64 + d0;
    for (int tt = 0; tt < 64; ++tt) a = fmaf(sc[tq * 64 + tt], vb[(size_t)tt * 2048], a);
    po[tq][d0] = a;
    __syncthreads();
    if (tid < 64) {
        float o = po[0][tid] + po[1][tid] + po[2][tid] + po[3][tid];
        g_o[((size_t)b * LQN + qi) * 1024 + hh * 64 + tid] = o;
    }
}

// ---------------- host-side launch helpers ----------------
template<int DOBIAS, int ACT, int SPLIT>
static void gemmT(const float* A, int lda, long long sA,
                  const float* W, int ldw, long long sW,
                  const float* bias, long long sB,
                  float* C, int ldc, long long sC,
                  int M, int N, int K, int nz)
{
    dim3 grid(N / 128, M / 128, nz);
    gemmT_k<DOBIAS, ACT, SPLIT><<<grid, 256>>>(A, lda, sA, W, ldw, sW, bias, sB, C, ldc, sC, K);
}

extern "C" void kernel_launch(void* const* d_in, const int* in_sizes, int n_in,
                              void* d_out, int out_size)
{
    (void)in_sizes; (void)n_in; (void)out_size;
    const float* x       = (const float*)d_in[0];
    const float* stem_W  = (const float*)d_in[1];
    const float* stem_b  = (const float*)d_in[2];
    const float* norm_w  = (const float*)d_in[3];
    const float* in_W    = (const float*)d_in[4];
    const float* conv_w  = (const float*)d_in[5];
    const float* conv_b  = (const float*)d_in[6];
    const float* xproj_W = (const float*)d_in[7];
    const float* dt_W    = (const float*)d_in[8];
    const float* dt_b    = (const float*)d_in[9];
    const float* A_log   = (const float*)d_in[10];
    const float* D_p     = (const float*)d_in[11];
    const float* out_W   = (const float*)d_in[12];
    const float* q       = (const float*)d_in[13];
    const float* kv_W    = (const float*)d_in[14];
    const float* po_W    = (const float*)d_in[15];
    const float* po_b    = (const float*)d_in[16];
    const float* h1_W    = (const float*)d_in[17];
    const float* h1_b    = (const float*)d_in[18];
    const float* h2_W    = (const float*)d_in[19];
    const float* h2_b    = (const float*)d_in[20];
    float* out = (float*)d_out;

    float *p_res, *p_h, *p_hn, *p_xz, *p_xc, *p_dt, *p_xdbl, *p_yp, *p_kv, *p_o, *p_po, *p_s1;
    cudaGetSymbolAddress((void**)&p_res,  g_res);
    cudaGetSymbolAddress((void**)&p_h,    g_h);
    cudaGetSymbolAddress((void**)&p_hn,   g_hn);
    cudaGetSymbolAddress((void**)&p_xz,   g_xz);
    cudaGetSymbolAddress((void**)&p_xc,   g_xc);
    cudaGetSymbolAddress((void**)&p_dt,   g_dt);
    cudaGetSymbolAddress((void**)&p_xdbl, g_xdbl);
    cudaGetSymbolAddress((void**)&p_yp,   g_yp);
    cudaGetSymbolAddress((void**)&p_kv,   g_kv);
    cudaGetSymbolAddress((void**)&p_o,    g_o);
    cudaGetSymbolAddress((void**)&p_po,   g_po);
    cudaGetSymbolAddress((void**)&p_s1,   g_s1);

    // stem: res = x @ stem_W^T + stem_b      (M=1024, N=1024, K=64)
    gemmT<1,0,0>(x, 64, 0, stem_W, 64, 0, stem_b, 0,
                 p_res, 1024, 0, TOKENS, 1024, 64, 1);

    for (int i = 0; i < 16; ++i) {
        // res += h0 + h1 (i>0); hn = LN(res)*norm_w[i]
        ln_k<<<TOKENS, 256>>>(i == 0 ? nullptr : p_h,
                              i == 0 ? nullptr : p_h + BLD,
                              p_res, norm_w + (size_t)i * 1024, p_hn);
        // xz (both dirs fused): N=4096
        gemmT<0,0,0>(p_hn, 1024, 0, in_W + (size_t)i * 4096 * 1024, 1024, 0,
                     nullptr, 0, p_xz, 4096, 0, TOKENS, 4096, 1024, 1);
        // depthwise conv + silu (both dirs)
        conv_k<<<4096, 256>>>(conv_w, conv_b, i);
        // xproj: N=96, dirs via blockIdx.z (skinny kernel)
        {
            dim3 grid((96 + BNN - 1) / BNN, TOKENS / 32, 2);
            gemm_k<32><<<grid, 256>>>(p_xc, 1024, BLD,
                                      xproj_W + (size_t)i * 2 * 96 * 1024, 1024, (long long)96 * 1024,
                                      p_xdbl, 96, XDB, TOKENS, 96, 1024);
        }
        // dt = softplus(xdbl[:, :64] @ dt_W^T + dt_b): K=64, dirs via z
        gemmT<1,2,0>(p_xdbl, 96, XDB,
                     dt_W + (size_t)i * 2 * 1024 * 64, 64, (long long)1024 * 64,
                     dt_b + (size_t)i * 2 * 1024, 1024,
                     p_dt, 1024, BLD, TOKENS, 1024, 64, 2);
        // selective scan (+x*Dp, *silu(z)) -> interleaved yp
        scan_k<<<dim3(16, 4, 2), 64>>>(A_log, D_p, i);
        // h0/h1 = yp[:, dir*1024:] @ out_W[i,dir]^T (split-K over dirs via z)
        gemmT<0,0,0>(p_yp, 2048, 1024,
                     out_W + (size_t)i * 2 * 1024 * 1024, 1024, (long long)1024 * 1024,
                     nullptr, 0, p_h, 1024, BLD, TOKENS, 1024, 1024, 2);
    }

    // final residual + LN
    ln_k<<<TOKENS, 256>>>(p_h, p_h + BLD, p_res, norm_w + (size_t)16 * 1024, p_hn);
    // kv projection: N=2048
    gemmT<0,0,0>(p_hn, 1024, 0, kv_W, 1024, 0, nullptr, 0,
                 p_kv, 2048, 0, TOKENS, 2048, 1024, 1);
    // attention
    attn_k<<<dim3(LQN, 16, 4), 256>>>(q);
    // s = silu(o @ po_W^T + po_b)   (M padded to 384; rows >=308 are deterministic junk)
    gemmT<1,1,0>(p_o, 1024, 0, po_W, 1024, 0, po_b, 0,
                 p_po, 1024, 0, MHP, 1024, 1024, 1);
    // s1 = silu(s @ h1_W^T + h1_b)
    gemmT<1,1,0>(p_po, 1024, 0, h1_W, 1024, 0, h1_b, 0,
                 p_s1, 1536, 0, MHP, 1536, 1024, 1);
    // s2 = s1 @ h2_W^T + h2_b, split-written as (a | b) into d_out (m<308 guarded)
    gemmT<1,0,1>(p_s1, 1536, 0, h2_W, 1536, 0, h2_b, 0,
                 out, 0, 0, MHP, 1536, 1536, 1);
}

// round 10
// speedup vs baseline: 2.1805x; 1.5362x over previous
#include <cuda_runtime.h>
#include <cuda_bf16.h>
#include <cstdint>

// ---------------- problem constants ----------------
#define LLEN   256
#define DDIM   1024
#define TOKENS 1024            // B*L
#define BLD    (1024*1024)     // TOKENS*D
#define XDB    (1024*96)       // TOKENS*96
#define LQN    77
#define MH     308             // B*LQ
#define MHP    384             // MH padded to 3*128
#define OUTF   768

// ---------------- scratch buffers (no runtime allocation allowed) ----------------
__device__ float g_res [BLD];
__device__ float g_h   [2*BLD];     // split-K partials h0 | h1
__device__ float g_hn  [BLD];
__device__ float g_xz  [4*BLD];     // [tok][4096]: dir0 x|z, dir1 x|z
__device__ float g_xc  [2*BLD];     // conv+silu output per dir
__device__ float g_dt  [2*BLD];
__device__ float g_xdbl[2*XDB];     // [dir][tok][96]
__device__ float g_yp  [2*BLD];     // [tok][2048]: dir0 | dir1
__device__ float g_kv  [2*BLD];     // [tok][2048]
__device__ float g_o   [MHP*1024];  // rows >= MH stay zero
__device__ float g_po  [MHP*1024];
__device__ float g_s1  [MHP*1536];

// ---------------- math helpers ----------------
__device__ __forceinline__ float siluf(float v){ return v / (1.f + __expf(-v)); }
__device__ __forceinline__ float softplusf(float v){ return v > 20.f ? v : log1pf(__expf(v)); }

__device__ __forceinline__ uint32_t tf32r(float x){
    uint32_t u; asm("cvt.rna.tf32.f32 %0, %1;" : "=r"(u) : "f"(x)); return u;
}
__device__ __forceinline__ void mma8(float* d, uint32_t a0, uint32_t a1, uint32_t a2, uint32_t a3,
                                     uint32_t b0, uint32_t b1){
    asm volatile(
        "mma.sync.aligned.m16n8k8.row.col.f32.tf32.tf32.f32 "
        "{%0,%1,%2,%3}, {%4,%5,%6,%7}, {%8,%9}, {%0,%1,%2,%3};\n"
        : "+f"(d[0]), "+f"(d[1]), "+f"(d[2]), "+f"(d[3])
        : "r"(a0), "r"(a1), "r"(a2), "r"(a3), "r"(b0), "r"(b1));
}

__device__ __forceinline__ float block_sum(float v, float* red){
    #pragma unroll
    for (int o = 16; o; o >>= 1) v += __shfl_xor_sync(0xffffffffu, v, o);
    int w = threadIdx.x >> 5, ln = threadIdx.x & 31;
    if (ln == 0) red[w] = v;
    __syncthreads();
    float t = (threadIdx.x < 8) ? red[threadIdx.x] : 0.f;
    #pragma unroll
    for (int o = 4; o; o >>= 1) t += __shfl_xor_sync(0xffffffffu, t, o);
    if (threadIdx.x == 0) red[0] = t;
    __syncthreads();
    t = red[0];
    __syncthreads();
    return t;
}
__device__ __forceinline__ float block_max(float v, float* red){
    #pragma unroll
    for (int o = 16; o; o >>= 1) v = fmaxf(v, __shfl_xor_sync(0xffffffffu, v, o));
    int w = threadIdx.x >> 5, ln = threadIdx.x & 31;
    if (ln == 0) red[w] = v;
    __syncthreads();
    float t = (threadIdx.x < 8) ? red[threadIdx.x] : -3.0e38f;
    #pragma unroll
    for (int o = 4; o; o >>= 1) t = fmaxf(t, __shfl_xor_sync(0xffffffffu, t, o));
    if (threadIdx.x == 0) red[0] = t;
    __syncthreads();
    t = red[0];
    __syncthreads();
    return t;
}

// ================= tf32 mma.sync GEMM: C[M,N] = act(A[M,K] @ W[N,K]^T + bias) =================
// CTA tile 128x128, 8 warps (2m x 4n), warp tile 64x32, K chunks of 32 (4 x m16n8k8).
// Smem [k][m]/[k][n] with stride 136 (== 8 mod 32) -> all fragment LDS.32 conflict-free.
// Requires M%128==0, K%32==0, A rows 16B-aligned; N guarded via Nreal (pad to 128 grid).
// blockIdx.z strides sA/sW/sB/sC. SPLIT: final (a|b) output epilogue with m<MH guard.
#define TS 136
template<int DOBIAS, int ACT, int SPLIT>
__global__ void __launch_bounds__(256, 2) mgemm_k(
    const float* __restrict__ A, int lda, long long sA,
    const float* __restrict__ W, int ldw, long long sW,
    const float* __restrict__ bias, long long sB,
    float* __restrict__ C, int ldc, long long sC,
    int K, int Nreal)
{
    __shared__ __align__(16) uint32_t As[32 * TS];
    __shared__ __align__(16) uint32_t Bs[32 * TS];

    if (sA) A += (size_t)blockIdx.z * sA;
    if (sW) W += (size_t)blockIdx.z * sW;
    if (sC) C += (size_t)blockIdx.z * sC;
    if (DOBIAS && sB) bias += (size_t)blockIdx.z * sB;

    const int tid  = threadIdx.x;
    const int lane = tid & 31;
    const int wid  = tid >> 5;
    const int wm   = wid >> 2;         // 0..1
    const int wn   = wid & 3;          // 0..3
    const int bm   = blockIdx.y * 128;
    const int bn   = blockIdx.x * 128;
    const int r4   = lane >> 2;        // 0..7
    const int c4   = lane & 3;         // 0..3

    float d[4][4][4];
    #pragma unroll
    for (int mt = 0; mt < 4; ++mt)
        #pragma unroll
        for (int nt = 0; nt < 4; ++nt)
            #pragma unroll
            for (int e = 0; e < 4; ++e) d[mt][nt][e] = 0.f;

    // staging: thread owns row srow, k-half sf (16 k each), 4 float4
    const int srow = tid >> 1;
    const int sf   = tid & 1;
    const float* Ap = A + (size_t)(bm + srow) * lda + sf * 16;
    const int nrow  = bn + srow;
    const bool bok  = (nrow < Nreal);
    const float* Wp = W + (size_t)(bok ? nrow : 0) * ldw + sf * 16;

    for (int k0 = 0; k0 < K; k0 += 32) {
        #pragma unroll
        for (int j = 0; j < 4; ++j) {
            float4 av = *(const float4*)(Ap + k0 + j * 4);
            float4 wv = bok ? *(const float4*)(Wp + k0 + j * 4)
                            : make_float4(0.f, 0.f, 0.f, 0.f);
            int kk = sf * 16 + j * 4;
            As[(kk + 0) * TS + srow] = tf32r(av.x);
            As[(kk + 1) * TS + srow] = tf32r(av.y);
            As[(kk + 2) * TS + srow] = tf32r(av.z);
            As[(kk + 3) * TS + srow] = tf32r(av.w);
            Bs[(kk + 0) * TS + srow] = tf32r(wv.x);
            Bs[(kk + 1) * TS + srow] = tf32r(wv.y);
            Bs[(kk + 2) * TS + srow] = tf32r(wv.z);
            Bs[(kk + 3) * TS + srow] = tf32r(wv.w);
        }
        __syncthreads();

        #pragma unroll
        for (int kt = 0; kt < 4; ++kt) {
            const int kb = kt * 8;
            uint32_t b0[4], b1[4];
            #pragma unroll
            for (int nt = 0; nt < 4; ++nt) {
                int nc = wn * 32 + nt * 8 + r4;
                b0[nt] = Bs[(kb + c4) * TS + nc];
                b1[nt] = Bs[(kb + c4 + 4) * TS + nc];
            }
            #pragma unroll
            for (int mt = 0; mt < 4; ++mt) {
                int mb = wm * 64 + mt * 16 + r4;
                uint32_t a0 = As[(kb + c4) * TS + mb];
                uint32_t a1 = As[(kb + c4) * TS + mb + 8];
                uint32_t a2 = As[(kb + c4 + 4) * TS + mb];
                uint32_t a3 = As[(kb + c4 + 4) * TS + mb + 8];
                #pragma unroll
                for (int nt = 0; nt < 4; ++nt)
                    mma8(d[mt][nt], a0, a1, a2, a3, b0[nt], b1[nt]);
            }
        }
        __syncthreads();
    }

    // ---- epilogue: c0/c1 are (row, col0/col0+1), c2/c3 the same at row+8 ----
    #pragma unroll
    for (int mt = 0; mt < 4; ++mt) {
        int row0 = bm + wm * 64 + mt * 16 + r4;
        #pragma unroll
        for (int nt = 0; nt < 4; ++nt) {
            int col0 = bn + wn * 32 + nt * 8 + c4 * 2;
            if (col0 >= Nreal) continue;
            float v0 = d[mt][nt][0], v1 = d[mt][nt][1];
            float v2 = d[mt][nt][2], v3 = d[mt][nt][3];
            if (DOBIAS) {
                float bz0 = bias[col0], bz1 = bias[col0 + 1];
                v0 += bz0; v1 += bz1; v2 += bz0; v3 += bz1;
            }
            if (ACT == 1)      { v0 = siluf(v0); v1 = siluf(v1); v2 = siluf(v2); v3 = siluf(v3); }
            else if (ACT == 2) { v0 = softplusf(v0); v1 = softplusf(v1);
                                 v2 = softplusf(v2); v3 = softplusf(v3); }
            if (SPLIT) {
                // out layout: a = s[:, :768] then b = s[:, 768:], each [MH][768]
                float* o0 = (col0 < OUTF)
                    ? (C + (size_t)row0 * OUTF + col0)
                    : (C + (size_t)MH * OUTF + (size_t)row0 * OUTF + (col0 - OUTF));
                if (row0 < MH)     *(float2*)o0 = make_float2(v0, v1);
                if (row0 + 8 < MH) *(float2*)(o0 + (size_t)8 * OUTF) = make_float2(v2, v3);
            } else {
                *(float2*)(C + (size_t)row0 * ldc + col0)       = make_float2(v0, v1);
                *(float2*)(C + (size_t)(row0 + 8) * ldc + col0) = make_float2(v2, v3);
            }
        }
    }
}

// ---------------- residual-add(s) + LayerNorm(*w) ----------------
__global__ void __launch_bounds__(256) ln_k(const float* __restrict__ add0,
                                            const float* __restrict__ add1,
                                            float* __restrict__ res,
                                            const float* __restrict__ w,
                                            float* __restrict__ out)
{
    __shared__ float red[8];
    int t = blockIdx.x;
    size_t base = (size_t)t * DDIM;
    int tid = threadIdx.x;
    float v[4];
    #pragma unroll
    for (int j = 0; j < 4; ++j) {
        int d = j * 256 + tid;
        float r = res[base + d];
        if (add0) { r += add0[base + d] + add1[base + d]; res[base + d] = r; }
        v[j] = r;
    }
    float s = v[0] + v[1] + v[2] + v[3];
    s = block_sum(s, red);
    float mean = s * (1.f / DDIM);
    float q = 0.f;
    #pragma unroll
    for (int j = 0; j < 4; ++j) { float d0 = v[j] - mean; q += d0 * d0; }
    q = block_sum(q, red);
    float inv = rsqrtf(q * (1.f / DDIM) + 1e-5f);
    #pragma unroll
    for (int j = 0; j < 4; ++j) {
        int d = j * 256 + tid;
        out[base + d] = (v[j] - mean) * inv * w[d];
    }
}

// ---------------- depthwise conv (dir0 causal, dir1 anti-causal) + bias + silu ----------------
__global__ void __launch_bounds__(256) conv_k(const float* __restrict__ cw,
                                              const float* __restrict__ cb,
                                              int layer)
{
    int g = blockIdx.x * 256 + threadIdx.x;
    int tok = g >> 10, d = g & 1023;
    int b = tok >> 8, t = tok & 255;
    const float* xz_b = g_xz + (size_t)b * 256 * 4096;
    {
        const float* w = cw + ((size_t)(layer * 2 + 0) * 1024 + d) * 4;
        float a = cb[(size_t)(layer * 2 + 0) * 1024 + d];
        #pragma unroll
        for (int j = 0; j < 4; ++j) {
            int ts = t - 3 + j;
            if (ts >= 0) a = fmaf(w[j], xz_b[(size_t)ts * 4096 + d], a);
        }
        g_xc[(size_t)tok * 1024 + d] = siluf(a);
    }
    {
        const float* w = cw + ((size_t)(layer * 2 + 1) * 1024 + d) * 4;
        float a = cb[(size_t)(layer * 2 + 1) * 1024 + d];
        #pragma unroll
        for (int j = 0; j < 4; ++j) {
            int ts = t + 3 - j;
            if (ts <= 255) a = fmaf(w[j], xz_b[(size_t)ts * 4096 + 2048 + d], a);
        }
        g_xc[(size_t)BLD + (size_t)tok * 1024 + d] = siluf(a);
    }
}

// ---------------- selective scan with next-step prefetch ----------------
__global__ void __launch_bounds__(64) scan_k(const float* __restrict__ A_log,
                                             const float* __restrict__ D_p,
                                             int layer)
{
    int dir = blockIdx.z, b = blockIdx.y;
    int d = blockIdx.x * 64 + threadIdx.x;
    size_t pbase = (size_t)((layer * 2 + dir) * 1024 + d);
    float Ar[16];
    const float* al = A_log + pbase * 16;
    #pragma unroll
    for (int n = 0; n < 16; ++n) Ar[n] = -__expf(al[n]);
    float Dp = D_p[pbase];
    float h[16];
    #pragma unroll
    for (int n = 0; n < 16; ++n) h[n] = 0.f;

    const float* dt_p = g_dt + (size_t)dir * BLD + (size_t)b * 256 * 1024 + d;
    const float* x_p  = g_xc + (size_t)dir * BLD + (size_t)b * 256 * 1024 + d;
    const float* z_p  = g_xz + (size_t)b * 256 * 4096 + dir * 2048 + 1024 + d;
    const float* bc   = g_xdbl + (size_t)dir * XDB + (size_t)b * 256 * 96;
    float* y_p = g_yp + (size_t)b * 256 * 2048 + dir * 1024 + d;

    int t   = dir ? 255 : 0;
    int stp = dir ? -1 : 1;

    float dt_c = dt_p[(size_t)t * 1024];
    float xv_c = x_p [(size_t)t * 1024];
    float zv_c = z_p [(size_t)t * 4096];
    float4 Bq[4], Cq[4];
    {
        const float4* xv4 = (const float4*)(bc + t * 96 + 64);
        #pragma unroll
        for (int qk = 0; qk < 4; ++qk) { Bq[qk] = xv4[qk]; Cq[qk] = xv4[qk + 4]; }
    }

    for (int s = 0; s < 256; ++s) {
        int tn = t + stp;
        float dt_nv = 0.f, xv_n = 0.f, zv_n = 0.f;
        float4 Bn[4], Cn[4];
        if (s < 255) {
            dt_nv = dt_p[(size_t)tn * 1024];
            xv_n  = x_p [(size_t)tn * 1024];
            zv_n  = z_p [(size_t)tn * 4096];
            const float4* xv4 = (const float4*)(bc + tn * 96 + 64);
            #pragma unroll
            for (int qk = 0; qk < 4; ++qk) { Bn[qk] = xv4[qk]; Cn[qk] = xv4[qk + 4]; }
        }

        float Bf[16], Cf[16];
        #pragma unroll
        for (int qk = 0; qk < 4; ++qk) {
            Bf[qk*4+0] = Bq[qk].x; Bf[qk*4+1] = Bq[qk].y; Bf[qk*4+2] = Bq[qk].z; Bf[qk*4+3] = Bq[qk].w;
            Cf[qk*4+0] = Cq[qk].x; Cf[qk*4+1] = Cq[qk].y; Cf[qk*4+2] = Cq[qk].z; Cf[qk*4+3] = Cq[qk].w;
        }

        float dx = dt_c * xv_c;
        float y = 0.f;
        #pragma unroll
        for (int n = 0; n < 16; ++n) {
            float wv = __expf(dt_c * Ar[n]);
            h[n] = fmaf(wv, h[n], dx * Bf[n]);
            y = fmaf(h[n], Cf[n], y);
        }
        y = fmaf(xv_c, Dp, y);
        y_p[(size_t)t * 2048] = y * siluf(zv_c);

        t = tn; dt_c = dt_nv; xv_c = xv_n; zv_c = zv_n;
        #pragma unroll
        for (int qk = 0; qk < 4; ++qk) { Bq[qk] = Bn[qk]; Cq[qk] = Cn[qk]; }
    }
}

// ---------------- cross-attention: one block per (qi, head, batch) ----------------
__global__ void __launch_bounds__(256) attn_k(const float* __restrict__ q)
{
    __shared__ float qs[64];
    __shared__ float sc[256];
    __shared__ float po[4][64];
    __shared__ float red[8];
    int qi = blockIdx.x, hh = blockIdx.y, b = blockIdx.z;
    int tid = threadIdx.x;
    if (tid < 64) qs[tid] = q[((size_t)hh * LQN + qi) * 64 + tid];
    __syncthreads();
    float s;
    {
        const float* kp = g_kv + ((size_t)(b * 256 + tid)) * 2048 + hh * 128;
        float a = 0.f;
        #pragma unroll 8
        for (int d0 = 0; d0 < 64; ++d0) a = fmaf(qs[d0], kp[d0], a);
        s = a * 0.125f;
    }
    float mx = block_max(s, red);
    float e  = __expf(s - mx);
    float Z  = block_sum(e, red);
    sc[tid] = e / Z;
    __syncthreads();
    int d0 = tid & 63, tq = tid >> 6;
    float a = 0.f;
    const float* vb = g_kv + ((size_t)(b * 256 + tq * 64)) * 2048 + hh * 128 + 64 + d0;
    for (int tt = 0; tt < 64; ++tt) a = fmaf(sc[tq * 64 + tt], vb[(size_t)tt * 2048], a);
    po[tq][d0] = a;
    __syncthreads();
    if (tid < 64) {
        float o = po[0][tid] + po[1][tid] + po[2][tid] + po[3][tid];
        g_o[((size_t)b * LQN + qi) * 1024 + hh * 64 + tid] = o;
    }
}

// ---------------- host-side launch helper ----------------
template<int DOBIAS, int ACT, int SPLIT>
static void mg(const float* A, int lda, long long sA,
               const float* W, int ldw, long long sW,
               const float* bias, long long sB,
               float* C, int ldc, long long sC,
               int M, int Nreal, int Npad, int K, int nz)
{
    dim3 grid(Npad / 128, M / 128, nz);
    mgemm_k<DOBIAS, ACT, SPLIT><<<grid, 256>>>(A, lda, sA, W, ldw, sW, bias, sB,
                                               C, ldc, sC, K, Nreal);
}

extern "C" void kernel_launch(void* const* d_in, const int* in_sizes, int n_in,
                              void* d_out, int out_size)
{
    (void)in_sizes; (void)n_in; (void)out_size;
    const float* x       = (const float*)d_in[0];
    const float* stem_W  = (const float*)d_in[1];
    const float* stem_b  = (const float*)d_in[2];
    const float* norm_w  = (const float*)d_in[3];
    const float* in_W    = (const float*)d_in[4];
    const float* conv_w  = (const float*)d_in[5];
    const float* conv_b  = (const float*)d_in[6];
    const float* xproj_W = (const float*)d_in[7];
    const float* dt_W    = (const float*)d_in[8];
    const float* dt_b    = (const float*)d_in[9];
    const float* A_log   = (const float*)d_in[10];
    const float* D_p     = (const float*)d_in[11];
    const float* out_W   = (const float*)d_in[12];
    const float* q       = (const float*)d_in[13];
    const float* kv_W    = (const float*)d_in[14];
    const float* po_W    = (const float*)d_in[15];
    const float* po_b    = (const float*)d_in[16];
    const float* h1_W    = (const float*)d_in[17];
    const float* h1_b    = (const float*)d_in[18];
    const float* h2_W    = (const float*)d_in[19];
    const float* h2_b    = (const float*)d_in[20];
    float* out = (float*)d_out;

    float *p_res, *p_h, *p_hn, *p_xz, *p_xc, *p_dt, *p_xdbl, *p_yp, *p_kv, *p_o, *p_po, *p_s1;
    cudaGetSymbolAddress((void**)&p_res,  g_res);
    cudaGetSymbolAddress((void**)&p_h,    g_h);
    cudaGetSymbolAddress((void**)&p_hn,   g_hn);
    cudaGetSymbolAddress((void**)&p_xz,   g_xz);
    cudaGetSymbolAddress((void**)&p_xc,   g_xc);
    cudaGetSymbolAddress((void**)&p_dt,   g_dt);
    cudaGetSymbolAddress((void**)&p_xdbl, g_xdbl);
    cudaGetSymbolAddress((void**)&p_yp,   g_yp);
    cudaGetSymbolAddress((void**)&p_kv,   g_kv);
    cudaGetSymbolAddress((void**)&p_o,    g_o);
    cudaGetSymbolAddress((void**)&p_po,   g_po);
    cudaGetSymbolAddress((void**)&p_s1,   g_s1);

    // stem: res = x @ stem_W^T + stem_b   (M=1024, N=1024, K=64)
    mg<1,0,0>(x, 64, 0, stem_W, 64, 0, stem_b, 0,
              p_res, 1024, 0, TOKENS, 1024, 1024, 64, 1);

    for (int i = 0; i < 16; ++i) {
        // res += h0 + h1 (i>0); hn = LN(res)*norm_w[i]
        ln_k<<<TOKENS, 256>>>(i == 0 ? nullptr : p_h,
                              i == 0 ? nullptr : p_h + BLD,
                              p_res, norm_w + (size_t)i * 1024, p_hn);
        // xz (both dirs fused): N=4096, K=1024
        mg<0,0,0>(p_hn, 1024, 0, in_W + (size_t)i * 4096 * 1024, 1024, 0,
                  nullptr, 0, p_xz, 4096, 0, TOKENS, 4096, 4096, 1024, 1);
        // depthwise conv + silu (both dirs)
        conv_k<<<4096, 256>>>(conv_w, conv_b, i);
        // xproj: N=96 (padded to 128 with guards), dirs via z
        mg<0,0,0>(p_xc, 1024, BLD,
                  xproj_W + (size_t)i * 2 * 96 * 1024, 1024, (long long)96 * 1024,
                  nullptr, 0, p_xdbl, 96, XDB, TOKENS, 96, 128, 1024, 2);
        // dt = softplus(xdbl[:, :64] @ dt_W^T + dt_b): N=1024, K=64, dirs via z
        mg<1,2,0>(p_xdbl, 96, XDB,
                  dt_W + (size_t)i * 2 * 1024 * 64, 64, (long long)1024 * 64,
                  dt_b + (size_t)i * 2 * 1024, 1024,
                  p_dt, 1024, BLD, TOKENS, 1024, 1024, 64, 2);
        // selective scan (+x*Dp, *silu(z)) -> interleaved yp
        scan_k<<<dim3(16, 4, 2), 64>>>(A_log, D_p, i);
        // h0/h1 = yp[:, dir*1024:] @ out_W[i,dir]^T (split-K over dirs via z)
        mg<0,0,0>(p_yp, 2048, 1024,
                  out_W + (size_t)i * 2 * 1024 * 1024, 1024, (long long)1024 * 1024,
                  nullptr, 0, p_h, 1024, BLD, TOKENS, 1024, 1024, 1024, 2);
    }

    // final residual + LN
    ln_k<<<TOKENS, 256>>>(p_h, p_h + BLD, p_res, norm_w + (size_t)16 * 1024, p_hn);
    // kv projection: N=2048, K=1024
    mg<0,0,0>(p_hn, 1024, 0, kv_W, 1024, 0, nullptr, 0,
              p_kv, 2048, 0, TOKENS, 2048, 2048, 1024, 1);
    // attention
    attn_k<<<dim3(LQN, 16, 4), 256>>>(q);
    // s = silu(o @ po_W^T + po_b)   (M padded to 384; pad rows deterministic)
    mg<1,1,0>(p_o, 1024, 0, po_W, 1024, 0, po_b, 0,
              p_po, 1024, 0, MHP, 1024, 1024, 1024, 1);
    // s1 = silu(s @ h1_W^T + h1_b)
    mg<1,1,0>(p_po, 1024, 0, h1_W, 1024, 0, h1_b, 0,
              p_s1, 1536, 0, MHP, 1536, 1536, 1024, 1);
    // s2 = s1 @ h2_W^T + h2_b, split-written as (a | b) into d_out (m<308 guarded)
    mg<1,0,1>(p_s1, 1536, 0, h2_W, 1536, 0, h2_b, 0,
              out, 0, 0, MHP, 1536, 1536, 1536, 1);
}